// round 8
// baseline (speedup 1.0000x reference)
#include <cuda_runtime.h>
#include <cstdint>

#define B_   4
#define H_   16
#define T_   2048
#define C_   1024
#define D_   64
#define BH_  64

__device__ float g_q[BH_*T_*D_];
__device__ float g_k[BH_*T_*D_];
__device__ float g_v[BH_*T_*D_];
__device__ float g_att[BH_*T_*D_];
__device__ float g_invZ[BH_*T_];

__device__ __forceinline__ float to_tf32(float f){
    uint32_t r; asm("cvt.rna.tf32.f32 %0, %1;" : "=r"(r) : "f"(f));
    return __uint_as_float(r);
}

__device__ __forceinline__ void mma8(float4 &c, const uint32_t* a, const uint32_t* b){
    asm volatile("mma.sync.aligned.m16n8k8.row.col.f32.tf32.tf32.f32 "
        "{%0,%1,%2,%3}, {%4,%5,%6,%7}, {%8,%9}, {%0,%1,%2,%3};"
        : "+f"(c.x), "+f"(c.y), "+f"(c.z), "+f"(c.w)
        : "r"(a[0]), "r"(a[1]), "r"(a[2]), "r"(a[3]), "r"(b[0]), "r"(b[1]));
}

// ---------------- fragment-major smem layouts ----------------
// A-frag: [mb(16 rows)][ks(8 k)][lane][4 regs]; lane=(m&7)*4+(k&3), reg=((m>>3)&1)+2*((k>>2)&1)
// B-frag: [nb(8 cols)][ks(8 k)][lane][2 regs]; lane=(n&7)*4+(k&3), reg=(k>>2)&1

__device__ __forceinline__ void stA_k4(float* Af, int KS, int m, int k, float4 v){
    int base = (((m>>4)*KS + (k>>3))*32 + ((m&7)*4))*4 + ((m>>3)&1) + 2*((k>>2)&1);
    Af[base]    = to_tf32(v.x);
    Af[base+4]  = to_tf32(v.y);
    Af[base+8]  = to_tf32(v.z);
    Af[base+12] = to_tf32(v.w);
}
__device__ __forceinline__ void stB_n4(float* Bf, int KS, int k, int n, float4 v){
    int base = (((n>>3)*KS + (k>>3))*32 + ((n&7)*4 + (k&3)))*2 + ((k>>2)&1);
    Bf[base]    = to_tf32(v.x);
    Bf[base+8]  = to_tf32(v.y);
    Bf[base+16] = to_tf32(v.z);
    Bf[base+24] = to_tf32(v.w);
}
__device__ __forceinline__ void stB_k4(float* Bf, int KS, int n, int k, float4 v){
    int base = (((n>>3)*KS + (k>>3))*32 + ((n&7)*4))*2 + ((k>>2)&1);
    Bf[base]   = to_tf32(v.x);
    Bf[base+2] = to_tf32(v.y);
    Bf[base+4] = to_tf32(v.z);
    Bf[base+6] = to_tf32(v.w);
}
__device__ __forceinline__ void stP1(float* Pf, int KS, int q, int s, float v){
    Pf[(((q>>4)*KS + (s>>3))*32 + ((q&7)*4 + (s&3)))*4 + ((q>>3)&1) + 2*((s>>2)&1)] = to_tf32(v);
}

#define LDA4(Af, KS, mb, ks, lane) (*(const uint4*)((Af) + ((((mb)*(KS))+(ks))*32 + (lane))*4))
#define LDB2(Bf, KS, nb, ks, lane) (*(const uint2*)((Bf) + ((((nb)*(KS))+(ks))*32 + (lane))*2))

// =====================================================================
// K1: QKV projection. Block 256(m) x 64(n), 8 warps (4m x 2n) of 64x32.
// k-chunk 16, register-staged double buffer. Static smem 40KB.
// =====================================================================
__global__ __launch_bounds__(256) void qkv_kernel(
    const float* __restrict__ x, const float* __restrict__ Wq,
    const float* __restrict__ Wk, const float* __restrict__ Wv)
{
    __shared__ float Ab[2][16*2*128];   // 16KB each
    __shared__ float Bb[2][8*2*64];     // 4KB each
    int tid=threadIdx.x, lane=tid&31, w=tid>>5;
    int g=lane>>2, tg=lane&3;
    int wm=w&3, wn=w>>2;
    int bh=blockIdx.y, b=bh>>4, h=bh&15;
    int m0=blockIdx.x*256;
    const float* W = (blockIdx.z==0?Wq:(blockIdx.z==1?Wk:Wv)) + (size_t)h*C_*D_;
    float* out = (blockIdx.z==0?g_q:(blockIdx.z==1?g_k:g_v)) + ((size_t)bh*T_+m0)*D_;
    const float* A = x + ((size_t)b*T_+m0)*C_;

    int am = (tid+0*256)>>2;   // per-thread fixed A row bases
    int ak = (tid&3)*4;
    int br = tid>>4, bn = (tid&15)*4;

    float4 c[4][4];
    #pragma unroll
    for(int i=0;i<4;i++)
        #pragma unroll
        for(int j=0;j<4;j++) c[i][j]=make_float4(0.f,0.f,0.f,0.f);

    float4 rA[4]; float4 rB;
    const int NC = C_/16;   // 64 chunks

    // prologue: chunk0 -> buf0; chunk1 -> regs
    #pragma unroll
    for(int j=0;j<4;j++){ int m=am+j*64; rA[j]=*(const float4*)(A+(size_t)m*C_+0+ak); }
    rB=*(const float4*)(W+(size_t)(0+br)*D_+bn);
    #pragma unroll
    for(int j=0;j<4;j++){ int m=am+j*64; stA_k4(Ab[0],2,m,ak,rA[j]); }
    stB_n4(Bb[0],2,br,bn,rB);
    #pragma unroll
    for(int j=0;j<4;j++){ int m=am+j*64; rA[j]=*(const float4*)(A+(size_t)m*C_+16+ak); }
    rB=*(const float4*)(W+(size_t)(16+br)*D_+bn);
    __syncthreads();

    for(int ch=0; ch<NC; ch++){
        int p=ch&1;
        if(ch+1<NC){
            int q=(ch+1)&1;
            #pragma unroll
            for(int j=0;j<4;j++){ int m=am+j*64; stA_k4(Ab[q],2,m,ak,rA[j]); }
            stB_n4(Bb[q],2,br,bn,rB);
        }
        if(ch+2<NC){
            int k0=(ch+2)*16;
            #pragma unroll
            for(int j=0;j<4;j++){ int m=am+j*64; rA[j]=*(const float4*)(A+(size_t)m*C_+k0+ak); }
            rB=*(const float4*)(W+(size_t)(k0+br)*D_+bn);
        }
        #pragma unroll
        for(int ks=0;ks<2;ks++){
            uint4 a[4]; uint2 bb2[4];
            #pragma unroll
            for(int i=0;i<4;i++) a[i]=LDA4(Ab[p],2,wm*4+i,ks,lane);
            #pragma unroll
            for(int j=0;j<4;j++) bb2[j]=LDB2(Bb[p],2,wn*4+j,ks,lane);
            #pragma unroll
            for(int i=0;i<4;i++)
                #pragma unroll
                for(int j=0;j<4;j++) mma8(c[i][j], (const uint32_t*)&a[i], (const uint32_t*)&bb2[j]);
        }
        __syncthreads();
    }

    #pragma unroll
    for(int i=0;i<4;i++){
        int m=wm*64+i*16+g;
        #pragma unroll
        for(int j=0;j<4;j++){
            int n=wn*32+j*8+2*tg;
            *(float2*)(out+(size_t)m*D_+n)     = make_float2(c[i][j].x, c[i][j].y);
            *(float2*)(out+(size_t)(m+8)*D_+n) = make_float2(c[i][j].z, c[i][j].w);
        }
    }
}

// =====================================================================
// K2: per-key Z via S^T = K.Q^T. Block: 128 keys x streamed 64-query tiles.
// 8 warps (2s x 4t) of 64x16. Static smem 48KB (zsh aliases Qf after loop).
// =====================================================================
__global__ __launch_bounds__(256) void colsum_kernel()
{
    __shared__ float Kf[8192];   // A-frag: 8 mb x 8 ks x 128  (32KB)
    __shared__ float Qf[4096];   // B-frag: 8 nb x 8 ks x 64   (16KB)
    int tid=threadIdx.x, lane=tid&31, w=tid>>5;
    int g=lane>>2, tg=lane&3;
    int wm=w&1, wn=w>>1;
    int bh=blockIdx.y, s0=blockIdx.x*128;
    const float* kb=g_k+(size_t)bh*T_*D_;
    const float* qb=g_q+(size_t)bh*T_*D_;

    #pragma unroll
    for(int i=0;i<8;i++){
        int idx=tid+i*256, s=idx>>4, kq=(idx&15)*4;
        stA_k4(Kf, 8, s, kq, *(const float4*)(kb+(size_t)(s0+s)*D_+kq));
    }

    float zrow[4][2];
    #pragma unroll
    for(int i=0;i<4;i++){ zrow[i][0]=0.f; zrow[i][1]=0.f; }

    for(int t0=s0; t0<T_; t0+=64){
        __syncthreads();
        #pragma unroll
        for(int i=0;i<4;i++){
            int idx=tid+i*256, t=idx>>4, kq=(idx&15)*4;
            stB_k4(Qf, 8, t, kq, *(const float4*)(qb+(size_t)(t0+t)*D_+kq));
        }
        __syncthreads();

        float4 c[4][2];
        #pragma unroll
        for(int i=0;i<4;i++){ c[i][0]=make_float4(0.f,0.f,0.f,0.f); c[i][1]=make_float4(0.f,0.f,0.f,0.f); }
        #pragma unroll
        for(int ks=0;ks<8;ks++){
            uint4 a[4]; uint2 bb[2];
            #pragma unroll
            for(int i=0;i<4;i++) a[i]=LDA4(Kf, 8, wm*4+i, ks, lane);
            #pragma unroll
            for(int j=0;j<2;j++) bb[j]=LDB2(Qf, 8, wn*2+j, ks, lane);
            #pragma unroll
            for(int i=0;i<4;i++)
                #pragma unroll
                for(int j=0;j<2;j++) mma8(c[i][j], (const uint32_t*)&a[i], (const uint32_t*)&bb[j]);
        }
        #pragma unroll
        for(int i=0;i<4;i++){
            int sr0=s0+wm*64+i*16+g, sr1=sr0+8;
            #pragma unroll
            for(int j=0;j<2;j++){
                int tc0=t0+wn*16+j*8+2*tg, tc1=tc0+1;
                float4 S=c[i][j];
                zrow[i][0] += (tc0>=sr0)?__expf(S.x*0.125f):0.f;
                zrow[i][0] += (tc1>=sr0)?__expf(S.y*0.125f):0.f;
                zrow[i][1] += (tc0>=sr1)?__expf(S.z*0.125f):0.f;
                zrow[i][1] += (tc1>=sr1)?__expf(S.w*0.125f):0.f;
            }
        }
    }
    // reduce: zsh aliases dead Qf
    float* zsh = Qf;
    __syncthreads();
    if(tid<128) zsh[tid]=0.f;
    __syncthreads();
    #pragma unroll
    for(int i=0;i<4;i++)
        #pragma unroll
        for(int rr=0;rr<2;rr++){
            float v=zrow[i][rr];
            v += __shfl_xor_sync(0xffffffffu, v, 1);
            v += __shfl_xor_sync(0xffffffffu, v, 2);
            if(tg==0) atomicAdd(&zsh[wm*64+i*16+g+rr*8], v);
        }
    __syncthreads();
    if(tid<128) g_invZ[(size_t)bh*T_+s0+tid]=1.0f/zsh[tid];
}

// =====================================================================
// K3: attention. Block 64 queries, 64-key tiles, 8 warps (2q x 4s / 2q x 4d)
// of 32x16. P aliases K buffer. Static smem 48KB.
// =====================================================================
__global__ __launch_bounds__(256) void attn_kernel()
{
    __shared__ float Qf [4096];   // A-frag Q (16KB)
    __shared__ float KPf[4096];   // B-frag K / A-frag P (16KB)
    __shared__ float Vf [4096];   // B-frag V (16KB)
    int tid=threadIdx.x, lane=tid&31, w=tid>>5;
    int g=lane>>2, tg=lane&3;
    int wm=w&1, wn=w>>1;
    int bh=blockIdx.y;
    int t0=((int)gridDim.x-1-(int)blockIdx.x)*64;   // big tiles first
    const float* qb=g_q+(size_t)bh*T_*D_;
    const float* kb=g_k+(size_t)bh*T_*D_;
    const float* vb=g_v+(size_t)bh*T_*D_;
    const float* iz=g_invZ+(size_t)bh*T_;

    #pragma unroll
    for(int i=0;i<4;i++){
        int idx=tid+i*256, t=idx>>4, kq=(idx&15)*4;
        stA_k4(Qf, 8, t, kq, *(const float4*)(qb+(size_t)(t0+t)*D_+kq));
    }

    float4 oacc[2][2];
    #pragma unroll
    for(int i=0;i<2;i++){ oacc[i][0]=make_float4(0.f,0.f,0.f,0.f); oacc[i][1]=make_float4(0.f,0.f,0.f,0.f); }

    for(int s0=0; s0<=t0; s0+=64){
        __syncthreads();   // prev stage2 readers done (covers Qf load on iter 0 via next sync)
        #pragma unroll
        for(int i=0;i<4;i++){
            int idx=tid+i*256, r=idx>>4, kq=(idx&15)*4;
            stB_k4(KPf, 8, r, kq, *(const float4*)(kb+(size_t)(s0+r)*D_+kq));
            stB_n4(Vf,  8, r, kq, *(const float4*)(vb+(size_t)(s0+r)*D_+kq));
        }
        __syncthreads();

        // stage1: S[64x64]=Q.K^T, warps 2q x 4s of 32x16
        float4 s1[2][2];
        #pragma unroll
        for(int i=0;i<2;i++){ s1[i][0]=make_float4(0.f,0.f,0.f,0.f); s1[i][1]=make_float4(0.f,0.f,0.f,0.f); }
        #pragma unroll
        for(int ks=0;ks<8;ks++){
            uint4 a[2]; uint2 bb[2];
            #pragma unroll
            for(int i=0;i<2;i++) a[i]=LDA4(Qf, 8, wm*2+i, ks, lane);
            #pragma unroll
            for(int j=0;j<2;j++) bb[j]=LDB2(KPf, 8, wn*2+j, ks, lane);
            #pragma unroll
            for(int i=0;i<2;i++)
                #pragma unroll
                for(int j=0;j<2;j++) mma8(s1[i][j], (const uint32_t*)&a[i], (const uint32_t*)&bb[j]);
        }
        __syncthreads();   // K reads done before P overwrites

        float izv0[2], izv1[2];
        #pragma unroll
        for(int j=0;j<2;j++){
            int sl0=wn*16+j*8+2*tg;
            izv0[j]=__ldg(iz+s0+sl0);
            izv1[j]=__ldg(iz+s0+sl0+1);
        }
        #pragma unroll
        for(int i=0;i<2;i++){
            int ql0=wm*32+i*16+g;
            int qg0=t0+ql0, qg1=qg0+8;
            #pragma unroll
            for(int j=0;j<2;j++){
                int sl0=wn*16+j*8+2*tg, sl1=sl0+1;
                int sg0=s0+sl0, sg1=sg0+1;
                float4 S=s1[i][j];
                float w00=(qg0>=sg0)?__expf(S.x*0.125f)*izv0[j]:0.f;
                float w01=(qg0>=sg1)?__expf(S.y*0.125f)*izv1[j]:0.f;
                float w10=(qg1>=sg0)?__expf(S.z*0.125f)*izv0[j]:0.f;
                float w11=(qg1>=sg1)?__expf(S.w*0.125f)*izv1[j]:0.f;
                stP1(KPf, 8, ql0,   sl0, w00);
                stP1(KPf, 8, ql0,   sl1, w01);
                stP1(KPf, 8, ql0+8, sl0, w10);
                stP1(KPf, 8, ql0+8, sl1, w11);
            }
        }
        __syncthreads();

        // stage2: O[64x64] += P.V, warps 2q x 4d of 32x16
        #pragma unroll
        for(int ks=0;ks<8;ks++){
            uint4 a[2]; uint2 bb[2];
            #pragma unroll
            for(int i=0;i<2;i++) a[i]=LDA4(KPf, 8, wm*2+i, ks, lane);
            #pragma unroll
            for(int j=0;j<2;j++) bb[j]=LDB2(Vf, 8, wn*2+j, ks, lane);
            #pragma unroll
            for(int i=0;i<2;i++)
                #pragma unroll
                for(int j=0;j<2;j++) mma8(oacc[i][j], (const uint32_t*)&a[i], (const uint32_t*)&bb[j]);
        }
    }

    float* ob=g_att+((size_t)bh*T_+t0)*D_;
    #pragma unroll
    for(int i=0;i<2;i++){
        int q=wm*32+i*16+g;
        #pragma unroll
        for(int j=0;j<2;j++){
            int d=wn*16+j*8+2*tg;
            *(float2*)(ob+(size_t)q*D_+d)     = make_float2(oacc[i][j].x, oacc[i][j].y);
            *(float2*)(ob+(size_t)(q+8)*D_+d) = make_float2(oacc[i][j].z, oacc[i][j].w);
        }
    }
}

// =====================================================================
// K4: output projection + bias. Block 128(m) x 128(n), 8 warps (2m x 4n)
// of 64x32. k-chunk 16, register-staged double buffer. Static smem 32KB.
// =====================================================================
__global__ __launch_bounds__(256) void oproj_kernel(
    const float* __restrict__ Wo, const float* __restrict__ bo, float* __restrict__ out)
{
    __shared__ float Ab[2][8*2*128];    // 8KB each
    __shared__ float Bb[2][16*2*64];    // 8KB each
    int tid=threadIdx.x, lane=tid&31, w=tid>>5;
    int g=lane>>2, tg=lane&3;
    int wm=w&1, wn=w>>1;
    int m0=blockIdx.x*128, n0=blockIdx.y*128;

    int am=tid>>2, ak=(tid&3)*4;        // A: rows am, am+64
    int br=tid>>5, bn=(tid&31)*4;       // B: rows br, br+8

    float4 c[4][4];
    #pragma unroll
    for(int i=0;i<4;i++)
        #pragma unroll
        for(int j=0;j<4;j++) c[i][j]=make_float4(0.f,0.f,0.f,0.f);

    float4 rA[2]; float4 rB[2];
    const int NC = C_/16;

    // A gather helper: k = k0+ak within one head (16 | 64)
    auto ldA = [&](int k0, int j)->float4{
        int m=m0+am+j*64, b=m>>11, t=m&2047;
        int k=k0+ak, hk=k>>6, dk=k&63;
        return *(const float4*)(g_att+(((size_t)(b*H_+hk))*T_+t)*D_+dk);
    };

    #pragma unroll
    for(int j=0;j<2;j++) rA[j]=ldA(0,j);
    #pragma unroll
    for(int j=0;j<2;j++) rB[j]=*(const float4*)(Wo+(size_t)(0+br+j*8)*C_+n0+bn);
    #pragma unroll
    for(int j=0;j<2;j++) stA_k4(Ab[0],2,am+j*64,ak,rA[j]);
    #pragma unroll
    for(int j=0;j<2;j++) stB_n4(Bb[0],2,br+j*8,bn,rB[j]);
    #pragma unroll
    for(int j=0;j<2;j++) rA[j]=ldA(16,j);
    #pragma unroll
    for(int j=0;j<2;j++) rB[j]=*(const float4*)(Wo+(size_t)(16+br+j*8)*C_+n0+bn);
    __syncthreads();

    for(int ch=0; ch<NC; ch++){
        int p=ch&1;
        if(ch+1<NC){
            int q=(ch+1)&1;
            #pragma unroll
            for(int j=0;j<2;j++) stA_k4(Ab[q],2,am+j*64,ak,rA[j]);
            #pragma unroll
            for(int j=0;j<2;j++) stB_n4(Bb[q],2,br+j*8,bn,rB[j]);
        }
        if(ch+2<NC){
            int k0=(ch+2)*16;
            #pragma unroll
            for(int j=0;j<2;j++) rA[j]=ldA(k0,j);
            #pragma unroll
            for(int j=0;j<2;j++) rB[j]=*(const float4*)(Wo+(size_t)(k0+br+j*8)*C_+n0+bn);
        }
        #pragma unroll
        for(int ks=0;ks<2;ks++){
            uint4 a[4]; uint2 bb2[4];
            #pragma unroll
            for(int i=0;i<4;i++) a[i]=LDA4(Ab[p],2,wm*4+i,ks,lane);
            #pragma unroll
            for(int j=0;j<4;j++) bb2[j]=LDB2(Bb[p],2,wn*4+j,ks,lane);
            #pragma unroll
            for(int i=0;i<4;i++)
                #pragma unroll
                for(int j=0;j<4;j++) mma8(c[i][j], (const uint32_t*)&a[i], (const uint32_t*)&bb2[j]);
        }
        __syncthreads();
    }

    #pragma unroll
    for(int i=0;i<4;i++){
        int m=m0+wm*64+i*16+g;
        #pragma unroll
        for(int j=0;j<4;j++){
            int n=n0+wn*32+j*8+2*tg;
            float b0v=bo[n], b1v=bo[n+1];
            *(float2*)(out+(size_t)m*C_+n)     = make_float2(c[i][j].x+b0v, c[i][j].y+b1v);
            *(float2*)(out+(size_t)(m+8)*C_+n) = make_float2(c[i][j].z+b0v, c[i][j].w+b1v);
        }
    }
}

// =====================================================================
extern "C" void kernel_launch(void* const* d_in, const int* in_sizes, int n_in,
                              void* d_out, int out_size)
{
    const float* x  = (const float*)d_in[0];
    const float* Wq = (const float*)d_in[1];
    const float* Wk = (const float*)d_in[2];
    const float* Wv = (const float*)d_in[3];
    const float* Wo = (const float*)d_in[4];
    const float* bo = (const float*)d_in[5];
    float* out = (float*)d_out;

    qkv_kernel   <<<dim3(T_/256, BH_, 3), 256>>>(x, Wq, Wk, Wv);
    colsum_kernel<<<dim3(T_/128, BH_),    256>>>();
    attn_kernel  <<<dim3(T_/64,  BH_),    256>>>();
    oproj_kernel <<<dim3((B_*T_)/128, C_/128), 256>>>(Wo, bo, out);
}

// round 9
// speedup vs baseline: 1.9308x; 1.9308x over previous
#include <cuda_runtime.h>
#include <cstdint>

#define B_   4
#define H_   16
#define T_   2048
#define C_   1024
#define D_   64
#define BH_  64

__device__ float g_q  [BH_*T_*D_];
__device__ float g_k  [BH_*T_*D_];
__device__ float g_v  [BH_*T_*D_];
__device__ float g_vt [BH_*D_*T_];     // V transposed: [bh][d][t]
__device__ float g_att[BH_*T_*D_];
__device__ float g_invZ[BH_*T_];
__device__ float g_wt [3*H_*D_*C_];    // Wq/Wk/Wv transposed: [z][h][d][c]
__device__ float g_wot[C_*C_];         // Wo transposed: [n][c]

__device__ __forceinline__ float to_tf32(float f){
    uint32_t r; asm("cvt.rna.tf32.f32 %0, %1;" : "=r"(r) : "f"(f));
    return __uint_as_float(r);
}
__device__ __forceinline__ void mma8(float4 &c, const uint32_t* a, const uint32_t* b){
    asm volatile("mma.sync.aligned.m16n8k8.row.col.f32.tf32.tf32.f32 "
        "{%0,%1,%2,%3}, {%4,%5,%6,%7}, {%8,%9}, {%0,%1,%2,%3};"
        : "+f"(c.x), "+f"(c.y), "+f"(c.z), "+f"(c.w)
        : "r"(a[0]), "r"(a[1]), "r"(a[2]), "r"(a[3]), "r"(b[0]), "r"(b[1]));
}
__device__ __forceinline__ void ldmA(uint32_t* r, uint32_t addr){
    asm volatile("ldmatrix.sync.aligned.m8n8.x4.shared.b16 {%0,%1,%2,%3}, [%4];"
        : "=r"(r[0]), "=r"(r[1]), "=r"(r[2]), "=r"(r[3]) : "r"(addr));
}
__device__ __forceinline__ void ldmB(uint32_t* r, uint32_t addr){
    asm volatile("ldmatrix.sync.aligned.m8n8.x2.shared.b16 {%0,%1}, [%2];"
        : "=r"(r[0]), "=r"(r[1]) : "r"(addr));
}
__device__ __forceinline__ void st4tf(float* p, float4 v){
    p[0]=to_tf32(v.x); p[1]=to_tf32(v.y); p[2]=to_tf32(v.z); p[3]=to_tf32(v.w);
}

// lane offsets for ldmatrix fragment gathers (tile row-major [row][k], stride PAD)
// A x4 (m16k8): matrices (rows0-7,k0-3),(rows8-15,k0-3),(rows0-7,k4-7),(rows8-15,k4-7)
// B x2 (n8k8):  matrices (n0-7,k0-3),(n0-7,k4-7)
#define ROWA(lane) (((lane)&7) + (((lane)>>3)&1)*8)
#define KOFA(lane) (((lane)>>4)*4)
#define ROWB(lane) ((lane)&7)
#define KOFB(lane) ((((lane)>>3)&1)*4)

// =====================================================================
// K0: batched 32x32 tiled transpose  src[z][R][C] -> dst[z][C][R]
// =====================================================================
__global__ __launch_bounds__(256) void transpose_k(
    const float* __restrict__ src, float* __restrict__ dst, int R, int C)
{
    __shared__ float ts[32][33];
    int bx=blockIdx.x*32, by=blockIdx.y*32;
    size_t off=(size_t)blockIdx.z*R*C;
    int x=threadIdx.x & 31, y0=threadIdx.x >> 5;   // 32 x 8
    #pragma unroll
    for(int i=0;i<32;i+=8){ int r=by+y0+i; ts[y0+i][x]=src[off+(size_t)r*C+bx+x]; }
    __syncthreads();
    #pragma unroll
    for(int i=0;i<32;i+=8){ int cc=bx+y0+i; dst[off+(size_t)cc*R+by+x]=ts[x][y0+i]; }
}

// =====================================================================
// K1: QKV projection. Block 256(t) x 64(d), 8 warps (4m x 2n) of 64x32.
// A = x tile [256][32] pad36; B = Wt tile [64][32] pad36. 46KB static.
// =====================================================================
__global__ __launch_bounds__(256) void qkv_kernel(const float* __restrict__ x)
{
    __shared__ float As[256*36];
    __shared__ float Bs[64*36];
    int tid=threadIdx.x, lane=tid&31, w=tid>>5;
    int g=lane>>2, tg=lane&3;
    int wm=w&3, wn=w>>2;
    int bh=blockIdx.y, b=bh>>4, h=bh&15, z=blockIdx.z;
    int m0=blockIdx.x*256;
    const float* Wt = g_wt + ((size_t)z*H_ + h)*D_*C_;       // [d][c]
    float* out = (z==0?g_q:(z==1?g_k:g_v)) + ((size_t)bh*T_+m0)*D_;
    const float* A = x + ((size_t)b*T_+m0)*C_;

    uint32_t asb=(uint32_t)__cvta_generic_to_shared(As);
    uint32_t bsb=(uint32_t)__cvta_generic_to_shared(Bs);
    uint32_t aoff=asb + (ROWA(lane)*36 + KOFA(lane))*4;
    uint32_t boff=bsb + (ROWB(lane)*36 + KOFB(lane))*4;

    float4 c[4][4];
    #pragma unroll
    for(int i=0;i<4;i++)
        #pragma unroll
        for(int j=0;j<4;j++) c[i][j]=make_float4(0.f,0.f,0.f,0.f);

    for(int k0=0;k0<C_;k0+=32){
        __syncthreads();
        #pragma unroll
        for(int i=0;i<8;i++){
            int idx=tid+i*256, r=idx>>3, c4=(idx&7)*4;
            st4tf(&As[r*36+c4], *(const float4*)(A+(size_t)r*C_+k0+c4));
        }
        #pragma unroll
        for(int i=0;i<2;i++){
            int idx=tid+i*256, r=idx>>3, c4=(idx&7)*4;
            st4tf(&Bs[r*36+c4], *(const float4*)(Wt+(size_t)r*C_+k0+c4));
        }
        __syncthreads();
        #pragma unroll
        for(int ks=0;ks<4;ks++){
            uint32_t a[4][4], bb[4][2];
            #pragma unroll
            for(int i=0;i<4;i++) ldmA(a[i], aoff + ((wm*4+i)*16*36 + ks*8)*4);
            #pragma unroll
            for(int j=0;j<4;j++) ldmB(bb[j], boff + ((wn*4+j)*8*36 + ks*8)*4);
            #pragma unroll
            for(int i=0;i<4;i++)
                #pragma unroll
                for(int j=0;j<4;j++) mma8(c[i][j], a[i], bb[j]);
        }
    }
    #pragma unroll
    for(int i=0;i<4;i++){
        int m=wm*64+i*16+g;
        #pragma unroll
        for(int j=0;j<4;j++){
            int n=wn*32+j*8+2*tg;
            *(float2*)(out+(size_t)m*D_+n)     = make_float2(c[i][j].x, c[i][j].y);
            *(float2*)(out+(size_t)(m+8)*D_+n) = make_float2(c[i][j].z, c[i][j].w);
        }
    }
}

// =====================================================================
// K2: per-key Z via S^T = K.Q^T. Block 64 keys, 64-query stream tiles.
// A = K tile [64][64] pad68; B = Q tile [64][64] pad68 (direct, no transform).
// 8 warps (2s x 4t) of 32x16. 35KB static.
// =====================================================================
__global__ __launch_bounds__(256) void colsum_kernel()
{
    __shared__ float Kf[64*68];
    __shared__ float Qf[64*68];
    __shared__ float zsh[64];
    int tid=threadIdx.x, lane=tid&31, w=tid>>5;
    int g=lane>>2, tg=lane&3;
    int wm=w&1, wn=w>>1;
    int bh=blockIdx.y, s0=blockIdx.x*64;
    const float* kb=g_k+(size_t)bh*T_*D_;
    const float* qb=g_q+(size_t)bh*T_*D_;

    uint32_t ksb=(uint32_t)__cvta_generic_to_shared(Kf);
    uint32_t qsb=(uint32_t)__cvta_generic_to_shared(Qf);
    uint32_t aoff=ksb + (ROWA(lane)*68 + KOFA(lane))*4;
    uint32_t boff=qsb + (ROWB(lane)*68 + KOFB(lane))*4;

    if(tid<64) zsh[tid]=0.f;
    #pragma unroll
    for(int i=0;i<4;i++){
        int idx=tid+i*256, r=idx>>4, c4=(idx&15)*4;
        st4tf(&Kf[r*68+c4], *(const float4*)(kb+(size_t)(s0+r)*D_+c4));
    }

    float zrow[2][2];
    zrow[0][0]=zrow[0][1]=zrow[1][0]=zrow[1][1]=0.f;

    for(int t0=s0; t0<T_; t0+=64){
        __syncthreads();
        #pragma unroll
        for(int i=0;i<4;i++){
            int idx=tid+i*256, r=idx>>4, c4=(idx&15)*4;
            st4tf(&Qf[r*68+c4], *(const float4*)(qb+(size_t)(t0+r)*D_+c4));
        }
        __syncthreads();

        float4 c[2][2];
        c[0][0]=c[0][1]=c[1][0]=c[1][1]=make_float4(0.f,0.f,0.f,0.f);
        #pragma unroll
        for(int ks=0;ks<8;ks++){
            uint32_t a[2][4], bb[2][2];
            #pragma unroll
            for(int i=0;i<2;i++) ldmA(a[i], aoff + ((wm*2+i)*16*68 + ks*8)*4);
            #pragma unroll
            for(int j=0;j<2;j++) ldmB(bb[j], boff + ((wn*2+j)*8*68 + ks*8)*4);
            #pragma unroll
            for(int i=0;i<2;i++)
                #pragma unroll
                for(int j=0;j<2;j++) mma8(c[i][j], a[i], bb[j]);
        }
        bool diag=(t0==s0);
        #pragma unroll
        for(int i=0;i<2;i++){
            int sr0=s0+wm*32+i*16+g, sr1=sr0+8;
            #pragma unroll
            for(int j=0;j<2;j++){
                int tc0=t0+wn*16+j*8+2*tg, tc1=tc0+1;
                float4 S=c[i][j];
                zrow[i][0] += (!diag||tc0>=sr0)?__expf(S.x*0.125f):0.f;
                zrow[i][0] += (!diag||tc1>=sr0)?__expf(S.y*0.125f):0.f;
                zrow[i][1] += (!diag||tc0>=sr1)?__expf(S.z*0.125f):0.f;
                zrow[i][1] += (!diag||tc1>=sr1)?__expf(S.w*0.125f):0.f;
            }
        }
    }
    __syncthreads();
    #pragma unroll
    for(int i=0;i<2;i++)
        #pragma unroll
        for(int rr=0;rr<2;rr++){
            float v=zrow[i][rr];
            v += __shfl_xor_sync(0xffffffffu, v, 1);
            v += __shfl_xor_sync(0xffffffffu, v, 2);
            if(tg==0) atomicAdd(&zsh[wm*32+i*16+g+rr*8], v);
        }
    __syncthreads();
    if(tid<64) g_invZ[(size_t)bh*T_+s0+tid]=1.0f/zsh[tid];
}

// =====================================================================
// K3: attention. Block 64 queries, 32-key tiles, 8 warps.
// stage1 (2q x 4s warps, 32x8): S=Q.K^T -> exp*invZ -> Pf [64][32]pad36
// stage2 (2q x 4d warps, 32x16): O += P.Vt   (Vt tile [64 d][32 s]pad36)
// 44.5KB static.
// =====================================================================
__global__ __launch_bounds__(256) void attn_kernel()
{
    __shared__ float Qf[64*68];    // [q][d]
    __shared__ float Kf[32*68];    // [s][d]
    __shared__ float Pf[64*36];    // [q][s]
    __shared__ float Vf[64*36];    // [d][s]
    int tid=threadIdx.x, lane=tid&31, w=tid>>5;
    int g=lane>>2, tg=lane&3;
    int wm=w&1, wn=w>>1;
    int bh=blockIdx.y;
    int t0=((int)gridDim.x-1-(int)blockIdx.x)*64;   // big tiles first
    const float* qb=g_q +(size_t)bh*T_*D_;
    const float* kb=g_k +(size_t)bh*T_*D_;
    const float* vtb=g_vt+(size_t)bh*D_*T_;
    const float* iz=g_invZ+(size_t)bh*T_;

    uint32_t qsb=(uint32_t)__cvta_generic_to_shared(Qf);
    uint32_t ksb=(uint32_t)__cvta_generic_to_shared(Kf);
    uint32_t psb=(uint32_t)__cvta_generic_to_shared(Pf);
    uint32_t vsb=(uint32_t)__cvta_generic_to_shared(Vf);
    uint32_t qAoff=qsb + (ROWA(lane)*68 + KOFA(lane))*4;
    uint32_t kBoff=ksb + (ROWB(lane)*68 + KOFB(lane))*4;
    uint32_t pAoff=psb + (ROWA(lane)*36 + KOFA(lane))*4;
    uint32_t vBoff=vsb + (ROWB(lane)*36 + KOFB(lane))*4;

    #pragma unroll
    for(int i=0;i<4;i++){
        int idx=tid+i*256, r=idx>>4, c4=(idx&15)*4;
        st4tf(&Qf[r*68+c4], *(const float4*)(qb+(size_t)(t0+r)*D_+c4));
    }

    float4 oacc[2][2];
    oacc[0][0]=oacc[0][1]=oacc[1][0]=oacc[1][1]=make_float4(0.f,0.f,0.f,0.f);

    for(int s0=0; s0<=t0+32; s0+=32){
        __syncthreads();   // prev tile's stage2 readers done; Qf load visible after next sync
        #pragma unroll
        for(int i=0;i<2;i++){
            int idx=tid+i*256, r=idx>>4, c4=(idx&15)*4;
            st4tf(&Kf[r*68+c4], *(const float4*)(kb+(size_t)(s0+r)*D_+c4));
        }
        #pragma unroll
        for(int i=0;i<2;i++){
            int idx=tid+i*256, r=idx>>3, c4=(idx&7)*4;
            st4tf(&Vf[r*36+c4], *(const float4*)(vtb+(size_t)r*T_+s0+c4));
        }
        __syncthreads();

        // stage1: S[64q x 32s], warp 32q x 8s (mb 2, nb 1)
        float4 s1[2];
        s1[0]=s1[1]=make_float4(0.f,0.f,0.f,0.f);
        #pragma unroll
        for(int ks=0;ks<8;ks++){
            uint32_t a[2][4], bb[2];
            #pragma unroll
            for(int i=0;i<2;i++) ldmA(a[i], qAoff + ((wm*2+i)*16*68 + ks*8)*4);
            ldmB(bb, kBoff + (wn*8*68 + ks*8)*4);
            mma8(s1[0], a[0], bb);
            mma8(s1[1], a[1], bb);
        }
        bool msk=(s0>=t0);
        int sl0=wn*8+2*tg, sl1=sl0+1;
        float iz0=__ldg(iz+s0+sl0), iz1=__ldg(iz+s0+sl1);
        #pragma unroll
        for(int i=0;i<2;i++){
            int ql0=wm*32+i*16+g;
            int qg0=t0+ql0, qg1=qg0+8;
            int sg0=s0+sl0, sg1=sg0+1;
            float4 S=s1[i];
            float w00=(!msk||qg0>=sg0)?__expf(S.x*0.125f)*iz0:0.f;
            float w01=(!msk||qg0>=sg1)?__expf(S.y*0.125f)*iz1:0.f;
            float w10=(!msk||qg1>=sg0)?__expf(S.z*0.125f)*iz0:0.f;
            float w11=(!msk||qg1>=sg1)?__expf(S.w*0.125f)*iz1:0.f;
            *(float2*)&Pf[ql0*36+sl0]     = make_float2(to_tf32(w00), to_tf32(w01));
            *(float2*)&Pf[(ql0+8)*36+sl0] = make_float2(to_tf32(w10), to_tf32(w11));
        }
        __syncthreads();   // Pf complete

        // stage2: O[64q x 64d] += P.Vt, warp 32q x 16d (mb 2, nb 2), ks 4
        #pragma unroll
        for(int ks=0;ks<4;ks++){
            uint32_t a[2][4], bb[2][2];
            #pragma unroll
            for(int i=0;i<2;i++) ldmA(a[i], pAoff + ((wm*2+i)*16*36 + ks*8)*4);
            #pragma unroll
            for(int j=0;j<2;j++) ldmB(bb[j], vBoff + ((wn*2+j)*8*36 + ks*8)*4);
            #pragma unroll
            for(int i=0;i<2;i++)
                #pragma unroll
                for(int j=0;j<2;j++) mma8(oacc[i][j], a[i], bb[j]);
        }
    }

    float* ob=g_att+((size_t)bh*T_+t0)*D_;
    #pragma unroll
    for(int i=0;i<2;i++){
        int q=wm*32+i*16+g;
        #pragma unroll
        for(int j=0;j<2;j++){
            int d=wn*16+j*8+2*tg;
            *(float2*)(ob+(size_t)q*D_+d)     = make_float2(oacc[i][j].x, oacc[i][j].y);
            *(float2*)(ob+(size_t)(q+8)*D_+d) = make_float2(oacc[i][j].z, oacc[i][j].w);
        }
    }
}

// =====================================================================
// K4: output projection + bias. Block 128(m) x 128(n), 8 warps (2m x 4n)
// of 64x32. A [128][32]pad36, B = Wot tile [128][32]pad36. 36.9KB static.
// =====================================================================
__global__ __launch_bounds__(256) void oproj_kernel(
    const float* __restrict__ bo, float* __restrict__ out)
{
    __shared__ float As[128*36];
    __shared__ float Bs[128*36];
    int tid=threadIdx.x, lane=tid&31, w=tid>>5;
    int g=lane>>2, tg=lane&3;
    int wm=w&1, wn=w>>1;
    int m0=blockIdx.x*128, n0=blockIdx.y*128;

    uint32_t asb=(uint32_t)__cvta_generic_to_shared(As);
    uint32_t bsb=(uint32_t)__cvta_generic_to_shared(Bs);
    uint32_t aoff=asb + (ROWA(lane)*36 + KOFA(lane))*4;
    uint32_t boff=bsb + (ROWB(lane)*36 + KOFB(lane))*4;

    float4 c[4][4];
    #pragma unroll
    for(int i=0;i<4;i++)
        #pragma unroll
        for(int j=0;j<4;j++) c[i][j]=make_float4(0.f,0.f,0.f,0.f);

    for(int k0=0;k0<C_;k0+=32){
        __syncthreads();
        #pragma unroll
        for(int i=0;i<4;i++){
            int idx=tid+i*256, m=idx>>3, kq=(idx&7)*4;
            int mg=m0+m, b=mg>>11, t=mg&2047;
            int k=k0+kq, hk=k>>6, dk=k&63;
            st4tf(&As[m*36+kq], *(const float4*)(g_att+(((size_t)(b*H_+hk))*T_+t)*D_+dk));
        }
        #pragma unroll
        for(int i=0;i<4;i++){
            int idx=tid+i*256, n=idx>>3, kq=(idx&7)*4;
            st4tf(&Bs[n*36+kq], *(const float4*)(g_wot+(size_t)(n0+n)*C_+k0+kq));
        }
        __syncthreads();
        #pragma unroll
        for(int ks=0;ks<4;ks++){
            uint32_t a[4][4], bb[4][2];
            #pragma unroll
            for(int i=0;i<4;i++) ldmA(a[i], aoff + ((wm*4+i)*16*36 + ks*8)*4);
            #pragma unroll
            for(int j=0;j<4;j++) ldmB(bb[j], boff + ((wn*4+j)*8*36 + ks*8)*4);
            #pragma unroll
            for(int i=0;i<4;i++)
                #pragma unroll
                for(int j=0;j<4;j++) mma8(c[i][j], a[i], bb[j]);
        }
    }
    #pragma unroll
    for(int i=0;i<4;i++){
        int m=m0+wm*64+i*16+g;
        #pragma unroll
        for(int j=0;j<4;j++){
            int n=n0+wn*32+j*8+2*tg;
            float b0v=bo[n], b1v=bo[n+1];
            *(float2*)(out+(size_t)m*C_+n)     = make_float2(c[i][j].x+b0v, c[i][j].y+b1v);
            *(float2*)(out+(size_t)(m+8)*C_+n) = make_float2(c[i][j].z+b0v, c[i][j].w+b1v);
        }
    }
}

// =====================================================================
extern "C" void kernel_launch(void* const* d_in, const int* in_sizes, int n_in,
                              void* d_out, int out_size)
{
    const float* x  = (const float*)d_in[0];
    const float* Wq = (const float*)d_in[1];
    const float* Wk = (const float*)d_in[2];
    const float* Wv = (const float*)d_in[3];
    const float* Wo = (const float*)d_in[4];
    const float* bo = (const float*)d_in[5];
    float* out = (float*)d_out;

    float* wt; cudaGetSymbolAddress((void**)&wt, g_wt);
    float* wot; cudaGetSymbolAddress((void**)&wot, g_wot);
    float* v;  cudaGetSymbolAddress((void**)&v,  g_v);
    float* vt; cudaGetSymbolAddress((void**)&vt, g_vt);

    // weight transposes: [h][c][d] -> [h][d][c]
    transpose_k<<<dim3(D_/32, C_/32, H_), 256>>>(Wq, wt,             C_, D_);
    transpose_k<<<dim3(D_/32, C_/32, H_), 256>>>(Wk, wt+  H_*D_*C_,  C_, D_);
    transpose_k<<<dim3(D_/32, C_/32, H_), 256>>>(Wv, wt+2*H_*D_*C_,  C_, D_);
    transpose_k<<<dim3(C_/32, C_/32, 1),  256>>>(Wo, wot,            C_, C_);

    qkv_kernel   <<<dim3(T_/256, BH_, 3), 256>>>(x);
    transpose_k  <<<dim3(D_/32, T_/32, BH_), 256>>>(v, vt, T_, D_);   // V -> [bh][d][t]
    colsum_kernel<<<dim3(T_/64,  BH_),    256>>>();
    attn_kernel  <<<dim3(T_/64,  BH_),    256>>>();
    oproj_kernel <<<dim3((B_*T_)/128, C_/128), 256>>>(bo, out);
}

// round 10
// speedup vs baseline: 3.4970x; 1.8111x over previous
#include <cuda_runtime.h>
#include <cuda_fp16.h>
#include <cstdint>

#define B_   4
#define H_   16
#define T_   2048
#define C_   1024
#define D_   64
#define BH_  64

__device__ float g_q  [BH_*T_*D_];
__device__ float g_k  [BH_*T_*D_];
__device__ float g_v  [BH_*T_*D_];
__device__ float g_att[BH_*T_*D_];
__device__ float g_invZ[BH_*T_];

// ---- fp16 m16n8k16 mma, fp32 accum ----
__device__ __forceinline__ void mma16(float4 &c, const uint32_t* a, const uint32_t* b){
    asm volatile("mma.sync.aligned.m16n8k16.row.col.f32.f16.f16.f32 "
        "{%0,%1,%2,%3}, {%4,%5,%6,%7}, {%8,%9}, {%0,%1,%2,%3};"
        : "+f"(c.x), "+f"(c.y), "+f"(c.z), "+f"(c.w)
        : "r"(a[0]), "r"(a[1]), "r"(a[2]), "r"(a[3]), "r"(b[0]), "r"(b[1]));
}
__device__ __forceinline__ void ldmA(uint32_t* r, uint32_t addr){
    asm volatile("ldmatrix.sync.aligned.m8n8.x4.shared.b16 {%0,%1,%2,%3}, [%4];"
        : "=r"(r[0]), "=r"(r[1]), "=r"(r[2]), "=r"(r[3]) : "r"(addr));
}
__device__ __forceinline__ void ldmB(uint32_t* r, uint32_t addr){
    asm volatile("ldmatrix.sync.aligned.m8n8.x2.shared.b16 {%0,%1}, [%2];"
        : "=r"(r[0]), "=r"(r[1]) : "r"(addr));
}
__device__ __forceinline__ void ldmBT(uint32_t* r, uint32_t addr){
    asm volatile("ldmatrix.sync.aligned.m8n8.x2.trans.shared.b16 {%0,%1}, [%2];"
        : "=r"(r[0]), "=r"(r[1]) : "r"(addr));
}
// convert 4 f32 -> 4 halves, single 8B store
__device__ __forceinline__ void st4h(__half* p, float4 v){
    __half2 h0 = __floats2half2_rn(v.x, v.y);
    __half2 h1 = __floats2half2_rn(v.z, v.w);
    uint2 u; u.x = *(uint32_t*)&h0; u.y = *(uint32_t*)&h1;
    *(uint2*)p = u;
}

// lane addressing (units: halves)
// A x4 (m16k16): matrices (r0-7,k0-7),(r8-15,k0-7),(r0-7,k8-15),(r8-15,k8-15)
#define ROWA(l) (((l)&7) + (((l)>>3)&1)*8)
#define KOFA(l) (((l)>>4)*8)
// B x2 non-trans ([n][k] tile): (n0-7,k0-7),(n0-7,k8-15)
#define ROWB(l) ((l)&7)
#define KOFB(l) ((((l)>>3)&1)*8)
// B x2 trans ([k][n] tile): k-rows (k0-7),(k8-15); n offset per nb
#define ROWT(l) (((l)&7) + (((l)>>3)&1)*8)

// =====================================================================
// K1: QKV projection. Block 256(t) x 64(d), 8 warps (4m x 2n) of 64x32.
// A = x tile [256][64+8]h; B = W tile [64 c][64+8 d]h via trans ldmatrix.
// k-chunk 64. 45KB static.
// =====================================================================
__global__ __launch_bounds__(256) void qkv_kernel(
    const float* __restrict__ x, const float* __restrict__ Wq,
    const float* __restrict__ Wk, const float* __restrict__ Wv)
{
    __shared__ __half As[256*72];   // 36864B
    __shared__ __half Bs[64*72];    // 9216B
    int tid=threadIdx.x, lane=tid&31, w=tid>>5;
    int g=lane>>2, tg=lane&3;
    int wm=w&3, wn=w>>2;
    int bh=blockIdx.y, b=bh>>4, h=bh&15, z=blockIdx.z;
    int m0=blockIdx.x*256;
    const float* W = (z==0?Wq:(z==1?Wk:Wv)) + (size_t)h*C_*D_;   // [c][d]
    float* out = (z==0?g_q:(z==1?g_k:g_v)) + ((size_t)bh*T_+m0)*D_;
    const float* A = x + ((size_t)b*T_+m0)*C_;

    uint32_t asb=(uint32_t)__cvta_generic_to_shared(As);
    uint32_t bsb=(uint32_t)__cvta_generic_to_shared(Bs);
    uint32_t aoff = asb + (ROWA(lane)*72 + KOFA(lane))*2;
    uint32_t btoff= bsb + (ROWT(lane)*72)*2;

    float4 c[4][4];
    #pragma unroll
    for(int i=0;i<4;i++)
        #pragma unroll
        for(int j=0;j<4;j++) c[i][j]=make_float4(0.f,0.f,0.f,0.f);

    for(int k0=0;k0<C_;k0+=64){
        __syncthreads();
        #pragma unroll
        for(int i=0;i<16;i++){
            int idx=tid+i*256, r=idx>>4, c4=(idx&15)*4;
            st4h(&As[r*72+c4], *(const float4*)(A+(size_t)r*C_+k0+c4));
        }
        #pragma unroll
        for(int i=0;i<4;i++){
            int idx=tid+i*256, r=idx>>4, c4=(idx&15)*4;
            st4h(&Bs[r*72+c4], *(const float4*)(W+(size_t)(k0+r)*D_+c4));
        }
        __syncthreads();
        #pragma unroll
        for(int ks=0;ks<4;ks++){
            uint32_t a[4][4], bb[4][2];
            #pragma unroll
            for(int i=0;i<4;i++) ldmA(a[i], aoff + ((wm*4+i)*16*72 + ks*16)*2);
            #pragma unroll
            for(int j=0;j<4;j++) ldmBT(bb[j], btoff + (ks*16*72 + (wn*4+j)*8)*2);
            #pragma unroll
            for(int i=0;i<4;i++)
                #pragma unroll
                for(int j=0;j<4;j++) mma16(c[i][j], a[i], bb[j]);
        }
    }
    #pragma unroll
    for(int i=0;i<4;i++){
        int m=wm*64+i*16+g;
        #pragma unroll
        for(int j=0;j<4;j++){
            int n=wn*32+j*8+2*tg;
            *(float2*)(out+(size_t)m*D_+n)     = make_float2(c[i][j].x, c[i][j].y);
            *(float2*)(out+(size_t)(m+8)*D_+n) = make_float2(c[i][j].z, c[i][j].w);
        }
    }
}

// =====================================================================
// K2: per-key Z via S^T = K.Q^T. Block 64 keys, 64-query stream tiles.
// A = K [64][72]h; B = Q [64][72]h (non-trans). 8 warps (2s x 4t) 32x16.
// =====================================================================
__global__ __launch_bounds__(256) void colsum_kernel()
{
    __shared__ __half Kf[64*72];
    __shared__ __half Qf[64*72];
    __shared__ float zsh[64];
    int tid=threadIdx.x, lane=tid&31, w=tid>>5;
    int g=lane>>2, tg=lane&3;
    int wm=w&1, wn=w>>1;
    int bh=blockIdx.y, s0=blockIdx.x*64;
    const float* kb=g_k+(size_t)bh*T_*D_;
    const float* qb=g_q+(size_t)bh*T_*D_;

    uint32_t ksb=(uint32_t)__cvta_generic_to_shared(Kf);
    uint32_t qsb=(uint32_t)__cvta_generic_to_shared(Qf);
    uint32_t aoff = ksb + (ROWA(lane)*72 + KOFA(lane))*2;
    uint32_t boff = qsb + (ROWB(lane)*72 + KOFB(lane))*2;

    if(tid<64) zsh[tid]=0.f;
    #pragma unroll
    for(int i=0;i<4;i++){
        int idx=tid+i*256, r=idx>>4, c4=(idx&15)*4;
        st4h(&Kf[r*72+c4], *(const float4*)(kb+(size_t)(s0+r)*D_+c4));
    }

    float zrow[2][2];
    zrow[0][0]=zrow[0][1]=zrow[1][0]=zrow[1][1]=0.f;

    for(int t0=s0; t0<T_; t0+=64){
        __syncthreads();
        #pragma unroll
        for(int i=0;i<4;i++){
            int idx=tid+i*256, r=idx>>4, c4=(idx&15)*4;
            st4h(&Qf[r*72+c4], *(const float4*)(qb+(size_t)(t0+r)*D_+c4));
        }
        __syncthreads();

        float4 c[2][2];
        c[0][0]=c[0][1]=c[1][0]=c[1][1]=make_float4(0.f,0.f,0.f,0.f);
        #pragma unroll
        for(int ks=0;ks<4;ks++){
            uint32_t a[2][4], bb[2][2];
            #pragma unroll
            for(int i=0;i<2;i++) ldmA(a[i], aoff + ((wm*2+i)*16*72 + ks*16)*2);
            #pragma unroll
            for(int j=0;j<2;j++) ldmB(bb[j], boff + ((wn*2+j)*8*72 + ks*16)*2);
            #pragma unroll
            for(int i=0;i<2;i++)
                #pragma unroll
                for(int j=0;j<2;j++) mma16(c[i][j], a[i], bb[j]);
        }
        bool diag=(t0==s0);
        #pragma unroll
        for(int i=0;i<2;i++){
            int sr0=s0+wm*32+i*16+g, sr1=sr0+8;
            #pragma unroll
            for(int j=0;j<2;j++){
                int tc0=t0+wn*16+j*8+2*tg, tc1=tc0+1;
                float4 S=c[i][j];
                zrow[i][0] += (!diag||tc0>=sr0)?__expf(S.x*0.125f):0.f;
                zrow[i][0] += (!diag||tc1>=sr0)?__expf(S.y*0.125f):0.f;
                zrow[i][1] += (!diag||tc0>=sr1)?__expf(S.z*0.125f):0.f;
                zrow[i][1] += (!diag||tc1>=sr1)?__expf(S.w*0.125f):0.f;
            }
        }
    }
    __syncthreads();
    #pragma unroll
    for(int i=0;i<2;i++)
        #pragma unroll
        for(int rr=0;rr<2;rr++){
            float v=zrow[i][rr];
            v += __shfl_xor_sync(0xffffffffu, v, 1);
            v += __shfl_xor_sync(0xffffffffu, v, 2);
            if(tg==0) atomicAdd(&zsh[wm*32+i*16+g+rr*8], v);
        }
    __syncthreads();
    if(tid<64) g_invZ[(size_t)bh*T_+s0+tid]=1.0f/zsh[tid];
}

// =====================================================================
// K3: attention. Block 64 queries, 32-key tiles, 8 warps.
// stage1 (2q x 4s, 32x8): S=Q.K^T -> exp*invZ -> Pf [64][32+8]h
// stage2 (2q x 4d, 32x16): O += P.V, V [32 s][72 d]h via trans ldmatrix.
// 23.5KB static.
// =====================================================================
__global__ __launch_bounds__(256) void attn_kernel()
{
    __shared__ __half Qf[64*72];   // [q][d] 9216B
    __shared__ __half Kf[32*72];   // [s][d] 4608B
    __shared__ __half Vf[32*72];   // [s][d] 4608B
    __shared__ __half Pf[64*40];   // [q][s] 5120B
    int tid=threadIdx.x, lane=tid&31, w=tid>>5;
    int g=lane>>2, tg=lane&3;
    int wm=w&1, wn=w>>1;
    int bh=blockIdx.y;
    int t0=((int)gridDim.x-1-(int)blockIdx.x)*64;   // big tiles first
    const float* qb=g_q+(size_t)bh*T_*D_;
    const float* kb=g_k+(size_t)bh*T_*D_;
    const float* vb=g_v+(size_t)bh*T_*D_;
    const float* iz=g_invZ+(size_t)bh*T_;

    uint32_t qsb=(uint32_t)__cvta_generic_to_shared(Qf);
    uint32_t ksb=(uint32_t)__cvta_generic_to_shared(Kf);
    uint32_t vsb=(uint32_t)__cvta_generic_to_shared(Vf);
    uint32_t psb=(uint32_t)__cvta_generic_to_shared(Pf);
    uint32_t qAoff = qsb + (ROWA(lane)*72 + KOFA(lane))*2;
    uint32_t kBoff = ksb + (ROWB(lane)*72 + KOFB(lane))*2;
    uint32_t vToff = vsb + (ROWT(lane)*72)*2;
    uint32_t pAoff = psb + (ROWA(lane)*40 + KOFA(lane))*2;

    #pragma unroll
    for(int i=0;i<4;i++){
        int idx=tid+i*256, r=idx>>4, c4=(idx&15)*4;
        st4h(&Qf[r*72+c4], *(const float4*)(qb+(size_t)(t0+r)*D_+c4));
    }

    float4 oacc[2][2];
    oacc[0][0]=oacc[0][1]=oacc[1][0]=oacc[1][1]=make_float4(0.f,0.f,0.f,0.f);

    for(int s0=0; s0<=t0+32; s0+=32){
        __syncthreads();   // prev stage2 readers done (covers Qf fill on iter 0 via next sync)
        #pragma unroll
        for(int i=0;i<2;i++){
            int idx=tid+i*256, r=idx>>4, c4=(idx&15)*4;
            st4h(&Kf[r*72+c4], *(const float4*)(kb+(size_t)(s0+r)*D_+c4));
            st4h(&Vf[r*72+c4], *(const float4*)(vb+(size_t)(s0+r)*D_+c4));
        }
        __syncthreads();

        // stage1: S[64q x 32s], warp 32q x 8s
        float4 s1[2];
        s1[0]=s1[1]=make_float4(0.f,0.f,0.f,0.f);
        #pragma unroll
        for(int ks=0;ks<4;ks++){
            uint32_t a[2][4], bb[2];
            #pragma unroll
            for(int i=0;i<2;i++) ldmA(a[i], qAoff + ((wm*2+i)*16*72 + ks*16)*2);
            ldmB(bb, kBoff + (wn*8*72 + ks*16)*2);
            mma16(s1[0], a[0], bb);
            mma16(s1[1], a[1], bb);
        }
        bool msk=(s0>=t0);
        int sl0=wn*8+2*tg, sl1=sl0+1;
        float iz0=__ldg(iz+s0+sl0), iz1=__ldg(iz+s0+sl1);
        #pragma unroll
        for(int i=0;i<2;i++){
            int ql0=wm*32+i*16+g;
            int qg0=t0+ql0, qg1=qg0+8;
            int sg0=s0+sl0, sg1=sg0+1;
            float4 S=s1[i];
            float w00=(!msk||qg0>=sg0)?__expf(S.x*0.125f)*iz0:0.f;
            float w01=(!msk||qg0>=sg1)?__expf(S.y*0.125f)*iz1:0.f;
            float w10=(!msk||qg1>=sg0)?__expf(S.z*0.125f)*iz0:0.f;
            float w11=(!msk||qg1>=sg1)?__expf(S.w*0.125f)*iz1:0.f;
            *(__half2*)&Pf[ql0*40+sl0]     = __floats2half2_rn(w00, w01);
            *(__half2*)&Pf[(ql0+8)*40+sl0] = __floats2half2_rn(w10, w11);
        }
        __syncthreads();   // Pf complete

        // stage2: O[64q x 64d] += P.V, warp 32q x 16d, k = 32s (ks<2)
        #pragma unroll
        for(int ks=0;ks<2;ks++){
            uint32_t a[2][4], bb[2][2];
            #pragma unroll
            for(int i=0;i<2;i++) ldmA(a[i], pAoff + ((wm*2+i)*16*40 + ks*16)*2);
            #pragma unroll
            for(int j=0;j<2;j++) ldmBT(bb[j], vToff + (ks*16*72 + (wn*2+j)*8)*2);
            #pragma unroll
            for(int i=0;i<2;i++)
                #pragma unroll
                for(int j=0;j<2;j++) mma16(oacc[i][j], a[i], bb[j]);
        }
    }

    float* ob=g_att+((size_t)bh*T_+t0)*D_;
    #pragma unroll
    for(int i=0;i<2;i++){
        int q=wm*32+i*16+g;
        #pragma unroll
        for(int j=0;j<2;j++){
            int d=wn*16+j*8+2*tg;
            *(float2*)(ob+(size_t)q*D_+d)     = make_float2(oacc[i][j].x, oacc[i][j].y);
            *(float2*)(ob+(size_t)(q+8)*D_+d) = make_float2(oacc[i][j].z, oacc[i][j].w);
        }
    }
}

// =====================================================================
// K4: output projection + bias. Block 128(m) x 128(n), 8 warps (2m x 4n)
// of 64x32. A [128][72]h; B = Wo tile [64 c][128+8 n]h via trans ldmatrix.
// k-chunk 64. 35KB static.
// =====================================================================
__global__ __launch_bounds__(256) void oproj_kernel(
    const float* __restrict__ Wo, const float* __restrict__ bo, float* __restrict__ out)
{
    __shared__ __half As[128*72];    // 18432B
    __shared__ __half Bs[64*136];    // 17408B
    int tid=threadIdx.x, lane=tid&31, w=tid>>5;
    int g=lane>>2, tg=lane&3;
    int wm=w&1, wn=w>>1;
    int m0=blockIdx.x*128, n0=blockIdx.y*128;

    uint32_t asb=(uint32_t)__cvta_generic_to_shared(As);
    uint32_t bsb=(uint32_t)__cvta_generic_to_shared(Bs);
    uint32_t aoff = asb + (ROWA(lane)*72 + KOFA(lane))*2;
    uint32_t btoff= bsb + (ROWT(lane)*136)*2;

    float4 c[4][4];
    #pragma unroll
    for(int i=0;i<4;i++)
        #pragma unroll
        for(int j=0;j<4;j++) c[i][j]=make_float4(0.f,0.f,0.f,0.f);

    for(int k0=0;k0<C_;k0+=64){
        int hk=k0>>6;                         // chunk == one head
        __syncthreads();
        #pragma unroll
        for(int i=0;i<8;i++){
            int idx=tid+i*256, r=idx>>4, c4=(idx&15)*4;
            int mg=m0+r, b=mg>>11, t=mg&2047;
            st4h(&As[r*72+c4], *(const float4*)(g_att+(((size_t)(b*H_+hk))*T_+t)*D_+c4));
        }
        #pragma unroll
        for(int i=0;i<8;i++){
            int idx=tid+i*256, r=idx>>5, c4=(idx&31)*4;
            st4h(&Bs[r*136+c4], *(const float4*)(Wo+(size_t)(k0+r)*C_+n0+c4));
        }
        __syncthreads();
        #pragma unroll
        for(int ks=0;ks<4;ks++){
            uint32_t a[4][4], bb[4][2];
            #pragma unroll
            for(int i=0;i<4;i++) ldmA(a[i], aoff + ((wm*4+i)*16*72 + ks*16)*2);
            #pragma unroll
            for(int j=0;j<4;j++) ldmBT(bb[j], btoff + (ks*16*136 + (wn*4+j)*8)*2);
            #pragma unroll
            for(int i=0;i<4;i++)
                #pragma unroll
                for(int j=0;j<4;j++) mma16(c[i][j], a[i], bb[j]);
        }
    }
    #pragma unroll
    for(int i=0;i<4;i++){
        int m=m0+wm*64+i*16+g;
        #pragma unroll
        for(int j=0;j<4;j++){
            int n=n0+wn*32+j*8+2*tg;
            float b0v=bo[n], b1v=bo[n+1];
            *(float2*)(out+(size_t)m*C_+n)     = make_float2(c[i][j].x+b0v, c[i][j].y+b1v);
            *(float2*)(out+(size_t)(m+8)*C_+n) = make_float2(c[i][j].z+b0v, c[i][j].w+b1v);
        }
    }
}

// =====================================================================
extern "C" void kernel_launch(void* const* d_in, const int* in_sizes, int n_in,
                              void* d_out, int out_size)
{
    const float* x  = (const float*)d_in[0];
    const float* Wq = (const float*)d_in[1];
    const float* Wk = (const float*)d_in[2];
    const float* Wv = (const float*)d_in[3];
    const float* Wo = (const float*)d_in[4];
    const float* bo = (const float*)d_in[5];
    float* out = (float*)d_out;

    qkv_kernel   <<<dim3(T_/256, BH_, 3), 256>>>(x, Wq, Wk, Wv);
    colsum_kernel<<<dim3(T_/64,  BH_),    256>>>();
    attn_kernel  <<<dim3(T_/64,  BH_),    256>>>();
    oproj_kernel <<<dim3((B_*T_)/128, C_/128), 256>>>(Wo, bo, out);
}

// round 11
// speedup vs baseline: 3.6105x; 1.0325x over previous
#include <cuda_runtime.h>
#include <cuda_fp16.h>
#include <cstdint>

#define B_   4
#define H_   16
#define T_   2048
#define C_   1024
#define D_   64
#define BH_  64

__device__ __half g_qh [BH_*T_*D_];
__device__ __half g_kh [BH_*T_*D_];
__device__ __half g_vh [BH_*T_*D_];
__device__ __half g_att[BH_*T_*D_];
__device__ float  g_invZ[BH_*T_];

// ---- fp16 m16n8k16 mma, fp32 accum ----
__device__ __forceinline__ void mma16(float4 &c, const uint32_t* a, const uint32_t* b){
    asm volatile("mma.sync.aligned.m16n8k16.row.col.f32.f16.f16.f32 "
        "{%0,%1,%2,%3}, {%4,%5,%6,%7}, {%8,%9}, {%0,%1,%2,%3};"
        : "+f"(c.x), "+f"(c.y), "+f"(c.z), "+f"(c.w)
        : "r"(a[0]), "r"(a[1]), "r"(a[2]), "r"(a[3]), "r"(b[0]), "r"(b[1]));
}
__device__ __forceinline__ void ldmA(uint32_t* r, uint32_t addr){
    asm volatile("ldmatrix.sync.aligned.m8n8.x4.shared.b16 {%0,%1,%2,%3}, [%4];"
        : "=r"(r[0]), "=r"(r[1]), "=r"(r[2]), "=r"(r[3]) : "r"(addr));
}
__device__ __forceinline__ void ldmB(uint32_t* r, uint32_t addr){
    asm volatile("ldmatrix.sync.aligned.m8n8.x2.shared.b16 {%0,%1}, [%2];"
        : "=r"(r[0]), "=r"(r[1]) : "r"(addr));
}
__device__ __forceinline__ void ldmBT(uint32_t* r, uint32_t addr){
    asm volatile("ldmatrix.sync.aligned.m8n8.x2.trans.shared.b16 {%0,%1}, [%2];"
        : "=r"(r[0]), "=r"(r[1]) : "r"(addr));
}
__device__ __forceinline__ void st4h(__half* p, float4 v){
    __half2 h0 = __floats2half2_rn(v.x, v.y);
    __half2 h1 = __floats2half2_rn(v.z, v.w);
    uint2 u; u.x = *(uint32_t*)&h0; u.y = *(uint32_t*)&h1;
    *(uint2*)p = u;
}

// lane addressing (units: halves)
#define ROWA(l) (((l)&7) + (((l)>>3)&1)*8)
#define KOFA(l) (((l)>>4)*8)
#define ROWB(l) ((l)&7)
#define KOFB(l) ((((l)>>3)&1)*8)
#define ROWT(l) (((l)&7) + (((l)>>3)&1)*8)

// =====================================================================
// K1: QKV projection. Block 256(t) x 64(d), 8 warps (4m x 2n) of 64x32.
// A = x [256][72]h; B = W [64 c][72 d]h via trans ldmatrix. Out: fp16.
// =====================================================================
__global__ __launch_bounds__(256) void qkv_kernel(
    const float* __restrict__ x, const float* __restrict__ Wq,
    const float* __restrict__ Wk, const float* __restrict__ Wv)
{
    __shared__ __half As[256*72];
    __shared__ __half Bs[64*72];
    int tid=threadIdx.x, lane=tid&31, w=tid>>5;
    int g=lane>>2, tg=lane&3;
    int wm=w&3, wn=w>>2;
    int bh=blockIdx.y, b=bh>>4, h=bh&15, z=blockIdx.z;
    int m0=blockIdx.x*256;
    const float* W = (z==0?Wq:(z==1?Wk:Wv)) + (size_t)h*C_*D_;
    __half* out = (z==0?g_qh:(z==1?g_kh:g_vh)) + ((size_t)bh*T_+m0)*D_;
    const float* A = x + ((size_t)b*T_+m0)*C_;

    uint32_t asb=(uint32_t)__cvta_generic_to_shared(As);
    uint32_t bsb=(uint32_t)__cvta_generic_to_shared(Bs);
    uint32_t aoff = asb + (ROWA(lane)*72 + KOFA(lane))*2;
    uint32_t btoff= bsb + (ROWT(lane)*72)*2;

    float4 c[4][4];
    #pragma unroll
    for(int i=0;i<4;i++)
        #pragma unroll
        for(int j=0;j<4;j++) c[i][j]=make_float4(0.f,0.f,0.f,0.f);

    for(int k0=0;k0<C_;k0+=64){
        __syncthreads();
        #pragma unroll
        for(int i=0;i<16;i++){
            int idx=tid+i*256, r=idx>>4, c4=(idx&15)*4;
            st4h(&As[r*72+c4], *(const float4*)(A+(size_t)r*C_+k0+c4));
        }
        #pragma unroll
        for(int i=0;i<4;i++){
            int idx=tid+i*256, r=idx>>4, c4=(idx&15)*4;
            st4h(&Bs[r*72+c4], *(const float4*)(W+(size_t)(k0+r)*D_+c4));
        }
        __syncthreads();
        #pragma unroll
        for(int ks=0;ks<4;ks++){
            uint32_t a[4][4], bb[4][2];
            #pragma unroll
            for(int i=0;i<4;i++) ldmA(a[i], aoff + ((wm*4+i)*16*72 + ks*16)*2);
            #pragma unroll
            for(int j=0;j<4;j++) ldmBT(bb[j], btoff + (ks*16*72 + (wn*4+j)*8)*2);
            #pragma unroll
            for(int i=0;i<4;i++)
                #pragma unroll
                for(int j=0;j<4;j++) mma16(c[i][j], a[i], bb[j]);
        }
    }
    #pragma unroll
    for(int i=0;i<4;i++){
        int m=wm*64+i*16+g;
        #pragma unroll
        for(int j=0;j<4;j++){
            int n=wn*32+j*8+2*tg;
            *(__half2*)(out+(size_t)m*D_+n)     = __floats2half2_rn(c[i][j].x, c[i][j].y);
            *(__half2*)(out+(size_t)(m+8)*D_+n) = __floats2half2_rn(c[i][j].z, c[i][j].w);
        }
    }
}

// =====================================================================
// K2: per-key Z via S^T = K.Q^T. Block 128 keys, 64-query stream tiles.
// A = K [128][72]h; B = Q [64][72]h. 8 warps (4s x 2t) of 32x32.
// 28KB static.
// =====================================================================
__global__ __launch_bounds__(256) void colsum_kernel()
{
    __shared__ __half Kf[128*72];
    __shared__ __half Qf[64*72];
    __shared__ float zsh[128];
    int tid=threadIdx.x, lane=tid&31, w=tid>>5;
    int g=lane>>2, tg=lane&3;
    int wm=w&3, wn=w>>2;
    int bh=blockIdx.y, s0=blockIdx.x*128;
    const __half* kb=g_kh+(size_t)bh*T_*D_;
    const __half* qb=g_qh+(size_t)bh*T_*D_;

    uint32_t ksb=(uint32_t)__cvta_generic_to_shared(Kf);
    uint32_t qsb=(uint32_t)__cvta_generic_to_shared(Qf);
    uint32_t aoff = ksb + (ROWA(lane)*72 + KOFA(lane))*2;
    uint32_t boff = qsb + (ROWB(lane)*72 + KOFB(lane))*2;

    if(tid<128) zsh[tid]=0.f;
    #pragma unroll
    for(int i=0;i<4;i++){
        int idx=tid+i*256, r=idx>>3, c8=(idx&7)*8;
        *(uint4*)&Kf[r*72+c8] = *(const uint4*)(kb+(size_t)(s0+r)*D_+c8);
    }

    float zrow[2][2];
    zrow[0][0]=zrow[0][1]=zrow[1][0]=zrow[1][1]=0.f;

    for(int t0=s0; t0<T_; t0+=64){
        __syncthreads();
        #pragma unroll
        for(int i=0;i<2;i++){
            int idx=tid+i*256, r=idx>>3, c8=(idx&7)*8;
            *(uint4*)&Qf[r*72+c8] = *(const uint4*)(qb+(size_t)(t0+r)*D_+c8);
        }
        __syncthreads();

        float4 c[2][4];
        #pragma unroll
        for(int i=0;i<2;i++)
            #pragma unroll
            for(int j=0;j<4;j++) c[i][j]=make_float4(0.f,0.f,0.f,0.f);
        #pragma unroll
        for(int ks=0;ks<4;ks++){
            uint32_t a[2][4], bb[4][2];
            #pragma unroll
            for(int i=0;i<2;i++) ldmA(a[i], aoff + ((wm*2+i)*16*72 + ks*16)*2);
            #pragma unroll
            for(int j=0;j<4;j++) ldmB(bb[j], boff + ((wn*4+j)*8*72 + ks*16)*2);
            #pragma unroll
            for(int i=0;i<2;i++)
                #pragma unroll
                for(int j=0;j<4;j++) mma16(c[i][j], a[i], bb[j]);
        }
        bool full = (t0 - s0) >= 128;
        #pragma unroll
        for(int i=0;i<2;i++){
            int sr0=s0+wm*32+i*16+g, sr1=sr0+8;
            #pragma unroll
            for(int j=0;j<4;j++){
                int tc0=t0+wn*32+j*8+2*tg, tc1=tc0+1;
                float4 S=c[i][j];
                zrow[i][0] += (full||tc0>=sr0)?__expf(S.x*0.125f):0.f;
                zrow[i][0] += (full||tc1>=sr0)?__expf(S.y*0.125f):0.f;
                zrow[i][1] += (full||tc0>=sr1)?__expf(S.z*0.125f):0.f;
                zrow[i][1] += (full||tc1>=sr1)?__expf(S.w*0.125f):0.f;
            }
        }
    }
    __syncthreads();
    #pragma unroll
    for(int i=0;i<2;i++)
        #pragma unroll
        for(int rr=0;rr<2;rr++){
            float v=zrow[i][rr];
            v += __shfl_xor_sync(0xffffffffu, v, 1);
            v += __shfl_xor_sync(0xffffffffu, v, 2);
            if(tg==0) atomicAdd(&zsh[wm*32+i*16+g+rr*8], v);
        }
    __syncthreads();
    if(tid<128) g_invZ[(size_t)bh*T_+s0+tid]=1.0f/zsh[tid];
}

// =====================================================================
// K3: attention. Block 128 queries, 32-key tiles, 8 warps.
// stage1 (4q x 2s, 32x16): S=Q.K^T -> exp*invZ -> Pf [128][40]h
// stage2 (4q x 2d, 32x32): O += P.V (V [32 s][72 d]h via trans ldmatrix).
// 38KB static.
// =====================================================================
__global__ __launch_bounds__(256) void attn_kernel()
{
    __shared__ __half Qf[128*72];   // [q][d] 18432B
    __shared__ __half Kf[32*72];    // [s][d] 4608B
    __shared__ __half Vf[32*72];    // [s][d] 4608B
    __shared__ __half Pf[128*40];   // [q][s] 10240B
    int tid=threadIdx.x, lane=tid&31, w=tid>>5;
    int g=lane>>2, tg=lane&3;
    int wq=w&3, wn=w>>2;
    int bh=blockIdx.y;
    int t0=((int)gridDim.x-1-(int)blockIdx.x)*128;   // big tiles first
    const __half* qb=g_qh+(size_t)bh*T_*D_;
    const __half* kb=g_kh+(size_t)bh*T_*D_;
    const __half* vb=g_vh+(size_t)bh*T_*D_;
    const float* iz=g_invZ+(size_t)bh*T_;

    uint32_t qsb=(uint32_t)__cvta_generic_to_shared(Qf);
    uint32_t ksb=(uint32_t)__cvta_generic_to_shared(Kf);
    uint32_t vsb=(uint32_t)__cvta_generic_to_shared(Vf);
    uint32_t psb=(uint32_t)__cvta_generic_to_shared(Pf);
    uint32_t qAoff = qsb + (ROWA(lane)*72 + KOFA(lane))*2;
    uint32_t kBoff = ksb + (ROWB(lane)*72 + KOFB(lane))*2;
    uint32_t vToff = vsb + (ROWT(lane)*72)*2;
    uint32_t pAoff = psb + (ROWA(lane)*40 + KOFA(lane))*2;

    #pragma unroll
    for(int i=0;i<4;i++){
        int idx=tid+i*256, r=idx>>3, c8=(idx&7)*8;
        *(uint4*)&Qf[r*72+c8] = *(const uint4*)(qb+(size_t)(t0+r)*D_+c8);
    }

    float4 oacc[2][4];
    #pragma unroll
    for(int i=0;i<2;i++)
        #pragma unroll
        for(int j=0;j<4;j++) oacc[i][j]=make_float4(0.f,0.f,0.f,0.f);

    for(int s0=0; s0<=t0+96; s0+=32){
        __syncthreads();   // prev stage2 readers done (covers Qf fill iter0 via next sync)
        {
            int r=tid>>3, c8=(tid&7)*8;   // 256 thr = 32 rows x 8 chunks
            *(uint4*)&Kf[r*72+c8] = *(const uint4*)(kb+(size_t)(s0+r)*D_+c8);
            *(uint4*)&Vf[r*72+c8] = *(const uint4*)(vb+(size_t)(s0+r)*D_+c8);
        }
        __syncthreads();

        // stage1: S[128q x 32s], warp 32q x 16s
        float4 s1[2][2];
        s1[0][0]=s1[0][1]=s1[1][0]=s1[1][1]=make_float4(0.f,0.f,0.f,0.f);
        #pragma unroll
        for(int ks=0;ks<4;ks++){
            uint32_t a[2][4], bb[2][2];
            #pragma unroll
            for(int i=0;i<2;i++) ldmA(a[i], qAoff + ((wq*2+i)*16*72 + ks*16)*2);
            #pragma unroll
            for(int j=0;j<2;j++) ldmB(bb[j], kBoff + ((wn*2+j)*8*72 + ks*16)*2);
            #pragma unroll
            for(int i=0;i<2;i++)
                #pragma unroll
                for(int j=0;j<2;j++) mma16(s1[i][j], a[i], bb[j]);
        }
        bool msk=(s0>=t0);
        #pragma unroll
        for(int i=0;i<2;i++){
            int ql0=wq*32+i*16+g;
            int qg0=t0+ql0, qg1=qg0+8;
            #pragma unroll
            for(int j=0;j<2;j++){
                int sl0=wn*16+j*8+2*tg, sl1=sl0+1;
                int sg0=s0+sl0, sg1=sg0+1;
                float iz0=__ldg(iz+sg0), iz1=__ldg(iz+sg1);
                float4 S=s1[i][j];
                float w00=(!msk||qg0>=sg0)?__expf(S.x*0.125f)*iz0:0.f;
                float w01=(!msk||qg0>=sg1)?__expf(S.y*0.125f)*iz1:0.f;
                float w10=(!msk||qg1>=sg0)?__expf(S.z*0.125f)*iz0:0.f;
                float w11=(!msk||qg1>=sg1)?__expf(S.w*0.125f)*iz1:0.f;
                *(__half2*)&Pf[ql0*40+sl0]     = __floats2half2_rn(w00, w01);
                *(__half2*)&Pf[(ql0+8)*40+sl0] = __floats2half2_rn(w10, w11);
            }
        }
        __syncthreads();   // Pf complete

        // stage2: O[128q x 64d] += P.V, warp 32q x 32d, k=32 (ks<2)
        #pragma unroll
        for(int ks=0;ks<2;ks++){
            uint32_t a[2][4], bb[4][2];
            #pragma unroll
            for(int i=0;i<2;i++) ldmA(a[i], pAoff + ((wq*2+i)*16*40 + ks*16)*2);
            #pragma unroll
            for(int j=0;j<4;j++) ldmBT(bb[j], vToff + (ks*16*72 + (wn*4+j)*8)*2);
            #pragma unroll
            for(int i=0;i<2;i++)
                #pragma unroll
                for(int j=0;j<4;j++) mma16(oacc[i][j], a[i], bb[j]);
        }
    }

    __half* ob=g_att+((size_t)bh*T_+t0)*D_;
    #pragma unroll
    for(int i=0;i<2;i++){
        int q=wq*32+i*16+g;
        #pragma unroll
        for(int j=0;j<4;j++){
            int d=wn*32+j*8+2*tg;
            *(__half2*)(ob+(size_t)q*D_+d)     = __floats2half2_rn(oacc[i][j].x, oacc[i][j].y);
            *(__half2*)(ob+(size_t)(q+8)*D_+d) = __floats2half2_rn(oacc[i][j].z, oacc[i][j].w);
        }
    }
}

// =====================================================================
// K4: output projection + bias. Block 128(m) x 128(n), 8 warps (2m x 4n)
// of 64x32. A [128][72]h from fp16 g_att; B = Wo [64 c][136 n]h trans.
// =====================================================================
__global__ __launch_bounds__(256) void oproj_kernel(
    const float* __restrict__ Wo, const float* __restrict__ bo, float* __restrict__ out)
{
    __shared__ __half As[128*72];
    __shared__ __half Bs[64*136];
    int tid=threadIdx.x, lane=tid&31, w=tid>>5;
    int g=lane>>2, tg=lane&3;
    int wm=w&1, wn=w>>1;
    int m0=blockIdx.x*128, n0=blockIdx.y*128;

    uint32_t asb=(uint32_t)__cvta_generic_to_shared(As);
    uint32_t bsb=(uint32_t)__cvta_generic_to_shared(Bs);
    uint32_t aoff = asb + (ROWA(lane)*72 + KOFA(lane))*2;
    uint32_t btoff= bsb + (ROWT(lane)*136)*2;

    float4 c[4][4];
    #pragma unroll
    for(int i=0;i<4;i++)
        #pragma unroll
        for(int j=0;j<4;j++) c[i][j]=make_float4(0.f,0.f,0.f,0.f);

    for(int k0=0;k0<C_;k0+=64){
        int hk=k0>>6;                         // chunk == one head
        __syncthreads();
        #pragma unroll
        for(int i=0;i<4;i++){
            int idx=tid+i*256, r=idx>>3, c8=(idx&7)*8;
            int mg=m0+r, b=mg>>11, t=mg&2047;
            *(uint4*)&As[r*72+c8] =
                *(const uint4*)(g_att+(((size_t)(b*H_+hk))*T_+t)*D_+c8);
        }
        #pragma unroll
        for(int i=0;i<8;i++){
            int idx=tid+i*256, r=idx>>5, c4=(idx&31)*4;
            st4h(&Bs[r*136+c4], *(const float4*)(Wo+(size_t)(k0+r)*C_+n0+c4));
        }
        __syncthreads();
        #pragma unroll
        for(int ks=0;ks<4;ks++){
            uint32_t a[4][4], bb[4][2];
            #pragma unroll
            for(int i=0;i<4;i++) ldmA(a[i], aoff + ((wm*4+i)*16*72 + ks*16)*2);
            #pragma unroll
            for(int j=0;j<4;j++) ldmBT(bb[j], btoff + (ks*16*136 + (wn*4+j)*8)*2);
            #pragma unroll
            for(int i=0;i<4;i++)
                #pragma unroll
                for(int j=0;j<4;j++) mma16(c[i][j], a[i], bb[j]);
        }
    }
    #pragma unroll
    for(int i=0;i<4;i++){
        int m=m0+wm*64+i*16+g;
        #pragma unroll
        for(int j=0;j<4;j++){
            int n=n0+wn*32+j*8+2*tg;
            float b0v=bo[n], b1v=bo[n+1];
            *(float2*)(out+(size_t)m*C_+n)     = make_float2(c[i][j].x+b0v, c[i][j].y+b1v);
            *(float2*)(out+(size_t)(m+8)*C_+n) = make_float2(c[i][j].z+b0v, c[i][j].w+b1v);
        }
    }
}

// =====================================================================
extern "C" void kernel_launch(void* const* d_in, const int* in_sizes, int n_in,
                              void* d_out, int out_size)
{
    const float* x  = (const float*)d_in[0];
    const float* Wq = (const float*)d_in[1];
    const float* Wk = (const float*)d_in[2];
    const float* Wv = (const float*)d_in[3];
    const float* Wo = (const float*)d_in[4];
    const float* bo = (const float*)d_in[5];
    float* out = (float*)d_out;

    qkv_kernel   <<<dim3(T_/256, BH_, 3), 256>>>(x, Wq, Wk, Wv);
    colsum_kernel<<<dim3(T_/128, BH_),    256>>>();
    attn_kernel  <<<dim3(T_/128, BH_),    256>>>();
    oproj_kernel <<<dim3((B_*T_)/128, C_/128), 256>>>(Wo, bo, out);
}

// round 12
// speedup vs baseline: 3.7235x; 1.0313x over previous
#include <cuda_runtime.h>
#include <cuda_fp16.h>
#include <cstdint>

#define B_   4
#define H_   16
#define T_   2048
#define C_   1024
#define D_   64
#define BH_  64

__device__ __half g_qh [BH_*T_*D_];
__device__ __half g_kh [BH_*T_*D_];
__device__ __half g_vh [BH_*T_*D_];
__device__ __half g_att[BH_*T_*D_];
__device__ float  g_invZ[BH_*T_];

// ---- fp16 m16n8k16 mma, fp32 accum ----
__device__ __forceinline__ void mma16(float4 &c, const uint32_t* a, const uint32_t* b){
    asm volatile("mma.sync.aligned.m16n8k16.row.col.f32.f16.f16.f32 "
        "{%0,%1,%2,%3}, {%4,%5,%6,%7}, {%8,%9}, {%0,%1,%2,%3};"
        : "+f"(c.x), "+f"(c.y), "+f"(c.z), "+f"(c.w)
        : "r"(a[0]), "r"(a[1]), "r"(a[2]), "r"(a[3]), "r"(b[0]), "r"(b[1]));
}
__device__ __forceinline__ void ldmA(uint32_t* r, uint32_t addr){
    asm volatile("ldmatrix.sync.aligned.m8n8.x4.shared.b16 {%0,%1,%2,%3}, [%4];"
        : "=r"(r[0]), "=r"(r[1]), "=r"(r[2]), "=r"(r[3]) : "r"(addr));
}
__device__ __forceinline__ void ldmB(uint32_t* r, uint32_t addr){
    asm volatile("ldmatrix.sync.aligned.m8n8.x2.shared.b16 {%0,%1}, [%2];"
        : "=r"(r[0]), "=r"(r[1]) : "r"(addr));
}
__device__ __forceinline__ void ldmBT(uint32_t* r, uint32_t addr){
    asm volatile("ldmatrix.sync.aligned.m8n8.x2.trans.shared.b16 {%0,%1}, [%2];"
        : "=r"(r[0]), "=r"(r[1]) : "r"(addr));
}
__device__ __forceinline__ void st4h(__half* p, float4 v){
    __half2 h0 = __floats2half2_rn(v.x, v.y);
    __half2 h1 = __floats2half2_rn(v.z, v.w);
    uint2 u; u.x = *(uint32_t*)&h0; u.y = *(uint32_t*)&h1;
    *(uint2*)p = u;
}
__device__ __forceinline__ void cpa16(uint32_t dst, const void* src){
    asm volatile("cp.async.cg.shared.global [%0], [%1], 16;" :: "r"(dst), "l"(src));
}
#define CP_COMMIT() asm volatile("cp.async.commit_group;" ::: "memory")
#define CP_WAIT0()  asm volatile("cp.async.wait_group 0;"  ::: "memory")

// lane addressing (units: halves)
#define ROWA(l) (((l)&7) + (((l)>>3)&1)*8)
#define KOFA(l) (((l)>>4)*8)
#define ROWB(l) ((l)&7)
#define KOFB(l) ((((l)>>3)&1)*8)
#define ROWT(l) (((l)&7) + (((l)>>3)&1)*8)

// =====================================================================
// K1: fused QKV projection. Block 128(t) x 192(n = 3z x 64d), one head.
// 8 warps (2m x 4n) of 64 x 48. A = x [128][72]h; B = 3 x W [64c][72d]h.
// 45KB static.
// =====================================================================
__global__ __launch_bounds__(256) void qkv_kernel(
    const float* __restrict__ x, const float* __restrict__ Wq,
    const float* __restrict__ Wk, const float* __restrict__ Wv)
{
    __shared__ __half As[128*72];      // 18432B
    __shared__ __half Bs[3*64*72];     // 27648B
    int tid=threadIdx.x, lane=tid&31, w=tid>>5;
    int g=lane>>2, tg=lane&3;
    int wm=w&1, wn=w>>1;
    int bh=blockIdx.y, b=bh>>4, h=bh&15;
    int m0=blockIdx.x*128;
    const float* Wz[3] = { Wq + (size_t)h*C_*D_, Wk + (size_t)h*C_*D_, Wv + (size_t)h*C_*D_ };
    __half* outz[3] = { g_qh + ((size_t)bh*T_+m0)*D_,
                        g_kh + ((size_t)bh*T_+m0)*D_,
                        g_vh + ((size_t)bh*T_+m0)*D_ };
    const float* A = x + ((size_t)b*T_+m0)*C_;

    uint32_t asb=(uint32_t)__cvta_generic_to_shared(As);
    uint32_t bsb=(uint32_t)__cvta_generic_to_shared(Bs);
    uint32_t aoff = asb + (ROWA(lane)*72 + KOFA(lane))*2;
    uint32_t btoff= bsb + (ROWT(lane)*72)*2;

    // per-j B-tile constants (n-block j: n = wn*48 + j*8)
    int zj[6], nlj[6];
    #pragma unroll
    for(int j=0;j<6;j++){ int n=wn*48+j*8; zj[j]=n>>6; nlj[j]=n&63; }

    float4 c[4][6];
    #pragma unroll
    for(int i=0;i<4;i++)
        #pragma unroll
        for(int j=0;j<6;j++) c[i][j]=make_float4(0.f,0.f,0.f,0.f);

    for(int k0=0;k0<C_;k0+=64){
        __syncthreads();
        // A fill: 128 rows x 16 float4 = 2048 -> 8/thread
        #pragma unroll
        for(int i=0;i<8;i++){
            int idx=tid+i*256, r=idx>>4, c4=(idx&15)*4;
            st4h(&As[r*72+c4], *(const float4*)(A+(size_t)r*C_+k0+c4));
        }
        // B fill: 3 x 64 rows x 16 float4 = 3072 -> 12/thread
        #pragma unroll
        for(int i=0;i<12;i++){
            int idx=tid+i*256, z=idx>>10, rem=idx&1023, r=rem>>4, c4=(rem&15)*4;
            st4h(&Bs[z*4608 + r*72 + c4], *(const float4*)(Wz[z]+(size_t)(k0+r)*D_+c4));
        }
        __syncthreads();
        #pragma unroll
        for(int ks=0;ks<4;ks++){
            uint32_t a[4][4], bb[6][2];
            #pragma unroll
            for(int i=0;i<4;i++) ldmA(a[i], aoff + ((wm*4+i)*16*72 + ks*16)*2);
            #pragma unroll
            for(int j=0;j<6;j++) ldmBT(bb[j], btoff + (zj[j]*4608 + ks*16*72 + nlj[j])*2);
            #pragma unroll
            for(int i=0;i<4;i++)
                #pragma unroll
                for(int j=0;j<6;j++) mma16(c[i][j], a[i], bb[j]);
        }
    }
    #pragma unroll
    for(int i=0;i<4;i++){
        int m=wm*64+i*16+g;
        #pragma unroll
        for(int j=0;j<6;j++){
            int d=nlj[j]+2*tg;
            __half* oz=outz[zj[j]];
            *(__half2*)(oz+(size_t)m*D_+d)     = __floats2half2_rn(c[i][j].x, c[i][j].y);
            *(__half2*)(oz+(size_t)(m+8)*D_+d) = __floats2half2_rn(c[i][j].z, c[i][j].w);
        }
    }
}

// =====================================================================
// K2: per-key Z via S^T = K.Q^T. Block 128 keys; 64-query stream tiles,
// double-buffered via cp.async. 8 warps (4s x 2t) of 32x32. 37KB static.
// =====================================================================
__global__ __launch_bounds__(256) void colsum_kernel()
{
    __shared__ __half Kf[128*72];     // 18432B
    __shared__ __half Qf[2][64*72];   // 2 x 9216B
    __shared__ float zsh[128];
    int tid=threadIdx.x, lane=tid&31, w=tid>>5;
    int g=lane>>2, tg=lane&3;
    int wm=w&3, wn=w>>2;
    int bh=blockIdx.y, s0=blockIdx.x*128;
    const __half* kb=g_kh+(size_t)bh*T_*D_;
    const __half* qb=g_qh+(size_t)bh*T_*D_;

    uint32_t ksb=(uint32_t)__cvta_generic_to_shared(Kf);
    uint32_t qsb[2]={(uint32_t)__cvta_generic_to_shared(Qf[0]),
                     (uint32_t)__cvta_generic_to_shared(Qf[1])};
    uint32_t aoff = ksb + (ROWA(lane)*72 + KOFA(lane))*2;

    if(tid<128) zsh[tid]=0.f;
    #pragma unroll
    for(int i=0;i<4;i++){
        int idx=tid+i*256, r=idx>>3, c8=(idx&7)*8;
        *(uint4*)&Kf[r*72+c8] = *(const uint4*)(kb+(size_t)(s0+r)*D_+c8);
    }
    // preload first Q tile into buf0
    {
        int r=tid>>3, c8=(tid&7)*8;    // 256 thr = 64 rows x ... (2 chunks/thread)
        #pragma unroll
        for(int i=0;i<2;i++){
            int idx=tid+i*256, rr=idx>>3, cc=(idx&7)*8;
            cpa16(qsb[0] + (rr*72+cc)*2, qb+(size_t)(s0+rr)*D_+cc);
        }
        (void)r; (void)c8;
    }
    CP_COMMIT();

    float zrow[2][2];
    zrow[0][0]=zrow[0][1]=zrow[1][0]=zrow[1][1]=0.f;

    for(int t0=s0; t0<T_; t0+=64){
        int p=((t0-s0)>>6)&1;
        CP_WAIT0();
        __syncthreads();   // Q[p] ready; prev MMAs on Q[p^1] done
        if(t0+64<T_){
            #pragma unroll
            for(int i=0;i<2;i++){
                int idx=tid+i*256, rr=idx>>3, cc=(idx&7)*8;
                cpa16(qsb[p^1] + (rr*72+cc)*2, qb+(size_t)(t0+64+rr)*D_+cc);
            }
        }
        CP_COMMIT();
        uint32_t boff = qsb[p] + (ROWB(lane)*72 + KOFB(lane))*2;

        float4 c[2][4];
        #pragma unroll
        for(int i=0;i<2;i++)
            #pragma unroll
            for(int j=0;j<4;j++) c[i][j]=make_float4(0.f,0.f,0.f,0.f);
        #pragma unroll
        for(int ks=0;ks<4;ks++){
            uint32_t a[2][4], bb[4][2];
            #pragma unroll
            for(int i=0;i<2;i++) ldmA(a[i], aoff + ((wm*2+i)*16*72 + ks*16)*2);
            #pragma unroll
            for(int j=0;j<4;j++) ldmB(bb[j], boff + ((wn*4+j)*8*72 + ks*16)*2);
            #pragma unroll
            for(int i=0;i<2;i++)
                #pragma unroll
                for(int j=0;j<4;j++) mma16(c[i][j], a[i], bb[j]);
        }
        bool full = (t0 - s0) >= 128;
        #pragma unroll
        for(int i=0;i<2;i++){
            int sr0=s0+wm*32+i*16+g, sr1=sr0+8;
            #pragma unroll
            for(int j=0;j<4;j++){
                int tc0=t0+wn*32+j*8+2*tg, tc1=tc0+1;
                float4 S=c[i][j];
                zrow[i][0] += (full||tc0>=sr0)?__expf(S.x*0.125f):0.f;
                zrow[i][0] += (full||tc1>=sr0)?__expf(S.y*0.125f):0.f;
                zrow[i][1] += (full||tc0>=sr1)?__expf(S.z*0.125f):0.f;
                zrow[i][1] += (full||tc1>=sr1)?__expf(S.w*0.125f):0.f;
            }
        }
    }
    __syncthreads();
    #pragma unroll
    for(int i=0;i<2;i++)
        #pragma unroll
        for(int rr=0;rr<2;rr++){
            float v=zrow[i][rr];
            v += __shfl_xor_sync(0xffffffffu, v, 1);
            v += __shfl_xor_sync(0xffffffffu, v, 2);
            if(tg==0) atomicAdd(&zsh[wm*32+i*16+g+rr*8], v);
        }
    __syncthreads();
    if(tid<128) g_invZ[(size_t)bh*T_+s0+tid]=1.0f/zsh[tid];
}

// =====================================================================
// K3: attention. Block 128 queries; 32-key tiles double-buffered via
// cp.async. stage1 (4q x 2s warps): S -> exp*invZ -> Pf; stage2 (4q x 2d):
// O += P.V. 46.6KB static.
// =====================================================================
__global__ __launch_bounds__(256) void attn_kernel()
{
    __shared__ __half Qf[128*72];      // 18432B
    __shared__ __half Kf[2][32*72];    // 2 x 4608B
    __shared__ __half Vf[2][32*72];    // 2 x 4608B
    __shared__ __half Pf[128*40];      // 10240B
    int tid=threadIdx.x, lane=tid&31, w=tid>>5;
    int g=lane>>2, tg=lane&3;
    int wq=w&3, wn=w>>2;
    int bh=blockIdx.y;
    int t0=((int)gridDim.x-1-(int)blockIdx.x)*128;   // big tiles first
    const __half* qb=g_qh+(size_t)bh*T_*D_;
    const __half* kb=g_kh+(size_t)bh*T_*D_;
    const __half* vb=g_vh+(size_t)bh*T_*D_;
    const float* iz=g_invZ+(size_t)bh*T_;

    uint32_t qsb=(uint32_t)__cvta_generic_to_shared(Qf);
    uint32_t ksb[2]={(uint32_t)__cvta_generic_to_shared(Kf[0]),
                     (uint32_t)__cvta_generic_to_shared(Kf[1])};
    uint32_t vsb[2]={(uint32_t)__cvta_generic_to_shared(Vf[0]),
                     (uint32_t)__cvta_generic_to_shared(Vf[1])};
    uint32_t psb=(uint32_t)__cvta_generic_to_shared(Pf);
    uint32_t qAoff = qsb + (ROWA(lane)*72 + KOFA(lane))*2;
    uint32_t pAoff = psb + (ROWA(lane)*40 + KOFA(lane))*2;

    // preload first K/V tile into buf0 (s0=0)
    {
        int r=tid>>3, c8=(tid&7)*8;    // 256 = 32 rows x 8 chunks
        cpa16(ksb[0] + (r*72+c8)*2, kb+(size_t)r*D_+c8);
        cpa16(vsb[0] + (r*72+c8)*2, vb+(size_t)r*D_+c8);
    }
    CP_COMMIT();
    // Q fill (regular)
    #pragma unroll
    for(int i=0;i<4;i++){
        int idx=tid+i*256, r=idx>>3, c8=(idx&7)*8;
        *(uint4*)&Qf[r*72+c8] = *(const uint4*)(qb+(size_t)(t0+r)*D_+c8);
    }

    float4 oacc[2][4];
    #pragma unroll
    for(int i=0;i<2;i++)
        #pragma unroll
        for(int j=0;j<4;j++) oacc[i][j]=make_float4(0.f,0.f,0.f,0.f);

    int send=t0+96;
    for(int s0=0; s0<=send; s0+=32){
        int p=(s0>>5)&1;
        CP_WAIT0();
        __syncthreads();   // K/V[p] ready; prev stage2 done (Pf + buf p^1 free)
        if(s0+32<=send){
            int r=tid>>3, c8=(tid&7)*8;
            cpa16(ksb[p^1] + (r*72+c8)*2, kb+(size_t)(s0+32+r)*D_+c8);
            cpa16(vsb[p^1] + (r*72+c8)*2, vb+(size_t)(s0+32+r)*D_+c8);
        }
        CP_COMMIT();
        uint32_t kBoff = ksb[p] + (ROWB(lane)*72 + KOFB(lane))*2;
        uint32_t vToff = vsb[p] + (ROWT(lane)*72)*2;

        // stage1: S[128q x 32s], warp 32q x 16s
        float4 s1[2][2];
        s1[0][0]=s1[0][1]=s1[1][0]=s1[1][1]=make_float4(0.f,0.f,0.f,0.f);
        #pragma unroll
        for(int ks=0;ks<4;ks++){
            uint32_t a[2][4], bb[2][2];
            #pragma unroll
            for(int i=0;i<2;i++) ldmA(a[i], qAoff + ((wq*2+i)*16*72 + ks*16)*2);
            #pragma unroll
            for(int j=0;j<2;j++) ldmB(bb[j], kBoff + ((wn*2+j)*8*72 + ks*16)*2);
            #pragma unroll
            for(int i=0;i<2;i++)
                #pragma unroll
                for(int j=0;j<2;j++) mma16(s1[i][j], a[i], bb[j]);
        }
        bool msk=(s0>=t0);
        #pragma unroll
        for(int i=0;i<2;i++){
            int ql0=wq*32+i*16+g;
            int qg0=t0+ql0, qg1=qg0+8;
            #pragma unroll
            for(int j=0;j<2;j++){
                int sl0=wn*16+j*8+2*tg, sl1=sl0+1;
                int sg0=s0+sl0, sg1=sg0+1;
                float iz0=__ldg(iz+sg0), iz1=__ldg(iz+sg1);
                float4 S=s1[i][j];
                float w00=(!msk||qg0>=sg0)?__expf(S.x*0.125f)*iz0:0.f;
                float w01=(!msk||qg0>=sg1)?__expf(S.y*0.125f)*iz1:0.f;
                float w10=(!msk||qg1>=sg0)?__expf(S.z*0.125f)*iz0:0.f;
                float w11=(!msk||qg1>=sg1)?__expf(S.w*0.125f)*iz1:0.f;
                *(__half2*)&Pf[ql0*40+sl0]     = __floats2half2_rn(w00, w01);
                *(__half2*)&Pf[(ql0+8)*40+sl0] = __floats2half2_rn(w10, w11);
            }
        }
        __syncthreads();   // Pf complete

        // stage2: O[128q x 64d] += P.V, warp 32q x 32d
        #pragma unroll
        for(int ks=0;ks<2;ks++){
            uint32_t a[2][4], bb[4][2];
            #pragma unroll
            for(int i=0;i<2;i++) ldmA(a[i], pAoff + ((wq*2+i)*16*40 + ks*16)*2);
            #pragma unroll
            for(int j=0;j<4;j++) ldmBT(bb[j], vToff + (ks*16*72 + (wn*4+j)*8)*2);
            #pragma unroll
            for(int i=0;i<2;i++)
                #pragma unroll
                for(int j=0;j<4;j++) mma16(oacc[i][j], a[i], bb[j]);
        }
    }

    __half* ob=g_att+((size_t)bh*T_+t0)*D_;
    #pragma unroll
    for(int i=0;i<2;i++){
        int q=wq*32+i*16+g;
        #pragma unroll
        for(int j=0;j<4;j++){
            int d=wn*32+j*8+2*tg;
            *(__half2*)(ob+(size_t)q*D_+d)     = __floats2half2_rn(oacc[i][j].x, oacc[i][j].y);
            *(__half2*)(ob+(size_t)(q+8)*D_+d) = __floats2half2_rn(oacc[i][j].z, oacc[i][j].w);
        }
    }
}

// =====================================================================
// K4: output projection + bias. Block 128(m) x 128(n), 8 warps (2m x 4n)
// of 64x32. A [128][72]h from fp16 g_att; B = Wo [64 c][136 n]h trans.
// =====================================================================
__global__ __launch_bounds__(256) void oproj_kernel(
    const float* __restrict__ Wo, const float* __restrict__ bo, float* __restrict__ out)
{
    __shared__ __half As[128*72];
    __shared__ __half Bs[64*136];
    int tid=threadIdx.x, lane=tid&31, w=tid>>5;
    int g=lane>>2, tg=lane&3;
    int wm=w&1, wn=w>>1;
    int m0=blockIdx.x*128, n0=blockIdx.y*128;

    uint32_t asb=(uint32_t)__cvta_generic_to_shared(As);
    uint32_t bsb=(uint32_t)__cvta_generic_to_shared(Bs);
    uint32_t aoff = asb + (ROWA(lane)*72 + KOFA(lane))*2;
    uint32_t btoff= bsb + (ROWT(lane)*136)*2;

    float4 c[4][4];
    #pragma unroll
    for(int i=0;i<4;i++)
        #pragma unroll
        for(int j=0;j<4;j++) c[i][j]=make_float4(0.f,0.f,0.f,0.f);

    for(int k0=0;k0<C_;k0+=64){
        int hk=k0>>6;                         // chunk == one head
        __syncthreads();
        #pragma unroll
        for(int i=0;i<4;i++){
            int idx=tid+i*256, r=idx>>3, c8=(idx&7)*8;
            int mg=m0+r, b=mg>>11, t=mg&2047;
            *(uint4*)&As[r*72+c8] =
                *(const uint4*)(g_att+(((size_t)(b*H_+hk))*T_+t)*D_+c8);
        }
        #pragma unroll
        for(int i=0;i<8;i++){
            int idx=tid+i*256, r=idx>>5, c4=(idx&31)*4;
            st4h(&Bs[r*136+c4], *(const float4*)(Wo+(size_t)(k0+r)*C_+n0+c4));
        }
        __syncthreads();
        #pragma unroll
        for(int ks=0;ks<4;ks++){
            uint32_t a[4][4], bb[4][2];
            #pragma unroll
            for(int i=0;i<4;i++) ldmA(a[i], aoff + ((wm*4+i)*16*72 + ks*16)*2);
            #pragma unroll
            for(int j=0;j<4;j++) ldmBT(bb[j], btoff + (ks*16*136 + (wn*4+j)*8)*2);
            #pragma unroll
            for(int i=0;i<4;i++)
                #pragma unroll
                for(int j=0;j<4;j++) mma16(c[i][j], a[i], bb[j]);
        }
    }
    #pragma unroll
    for(int i=0;i<4;i++){
        int m=m0+wm*64+i*16+g;
        #pragma unroll
        for(int j=0;j<4;j++){
            int n=n0+wn*32+j*8+2*tg;
            float b0v=bo[n], b1v=bo[n+1];
            *(float2*)(out+(size_t)m*C_+n)     = make_float2(c[i][j].x+b0v, c[i][j].y+b1v);
            *(float2*)(out+(size_t)m*C_+n)     = make_float2(c[i][j].x+b0v, c[i][j].y+b1v);
            *(float2*)(out+(size_t)(m+8)*C_+n) = make_float2(c[i][j].z+b0v, c[i][j].w+b1v);
        }
    }
}

// =====================================================================
extern "C" void kernel_launch(void* const* d_in, const int* in_sizes, int n_in,
                              void* d_out, int out_size)
{
    const float* x  = (const float*)d_in[0];
    const float* Wq = (const float*)d_in[1];
    const float* Wk = (const float*)d_in[2];
    const float* Wv = (const float*)d_in[3];
    const float* Wo = (const float*)d_in[4];
    const float* bo = (const float*)d_in[5];
    float* out = (float*)d_out;

    qkv_kernel   <<<dim3(T_/128, BH_),    256>>>(x, Wq, Wk, Wv);
    colsum_kernel<<<dim3(T_/128, BH_),    256>>>();
    attn_kernel  <<<dim3(T_/128, BH_),    256>>>();
    oproj_kernel <<<dim3((B_*T_)/128, C_/128), 256>>>(Wo, bo, out);
}

// round 14
// speedup vs baseline: 3.7716x; 1.0129x over previous
#include <cuda_runtime.h>
#include <cuda_fp16.h>
#include <cstdint>

#define B_   4
#define H_   16
#define T_   2048
#define C_   1024
#define D_   64
#define BH_  64

__device__ __half g_qh [BH_*T_*D_];
__device__ __half g_kh [BH_*T_*D_];
__device__ __half g_vh [BH_*T_*D_];
__device__ __half g_att[BH_*T_*D_];
__device__ float  g_invZ[BH_*T_];
__device__ __half g_xh [B_*T_*C_];       // x fp16
__device__ __half g_wh [3*H_*C_*D_];     // Wq/Wk/Wv fp16, layout [z][h][c][d]
__device__ __half g_woh[C_*C_];          // Wo fp16, layout [c][n]

// ================= helpers =================
__device__ __forceinline__ void mma16(float4 &c, const uint32_t* a, const uint32_t* b){
    asm volatile("mma.sync.aligned.m16n8k16.row.col.f32.f16.f16.f32 "
        "{%0,%1,%2,%3}, {%4,%5,%6,%7}, {%8,%9}, {%0,%1,%2,%3};"
        : "+f"(c.x), "+f"(c.y), "+f"(c.z), "+f"(c.w)
        : "r"(a[0]), "r"(a[1]), "r"(a[2]), "r"(a[3]), "r"(b[0]), "r"(b[1]));
}
__device__ __forceinline__ void ldmA(uint32_t* r, uint32_t addr){
    asm volatile("ldmatrix.sync.aligned.m8n8.x4.shared.b16 {%0,%1,%2,%3}, [%4];"
        : "=r"(r[0]), "=r"(r[1]), "=r"(r[2]), "=r"(r[3]) : "r"(addr));
}
__device__ __forceinline__ void ldmB(uint32_t* r, uint32_t addr){
    asm volatile("ldmatrix.sync.aligned.m8n8.x2.shared.b16 {%0,%1}, [%2];"
        : "=r"(r[0]), "=r"(r[1]) : "r"(addr));
}
__device__ __forceinline__ void ldmBT(uint32_t* r, uint32_t addr){
    asm volatile("ldmatrix.sync.aligned.m8n8.x2.trans.shared.b16 {%0,%1}, [%2];"
        : "=r"(r[0]), "=r"(r[1]) : "r"(addr));
}
__device__ __forceinline__ void cpa16(uint32_t dst, const void* src){
    asm volatile("cp.async.cg.shared.global [%0], [%1], 16;" :: "r"(dst), "l"(src));
}
#define CP_COMMIT() asm volatile("cp.async.commit_group;" ::: "memory")
#define CP_WAIT0()  asm volatile("cp.async.wait_group 0;"  ::: "memory")
#define CP_WAIT1()  asm volatile("cp.async.wait_group 1;"  ::: "memory")

// lane addressing (units: halves)
#define ROWA(l) (((l)&7) + (((l)>>3)&1)*8)
#define KOFA(l) (((l)>>4)*8)
#define ROWB(l) ((l)&7)
#define KOFB(l) ((((l)>>3)&1)*8)
#define ROWT(l) (((l)&7) + (((l)>>3)&1)*8)

// ================= prep: fp32 -> fp16 converts =================
__global__ __launch_bounds__(256) void cvt_kernel(const float* __restrict__ src, __half* __restrict__ dst){
    int i0 = (blockIdx.x*256 + threadIdx.x)*8;
    #pragma unroll
    for(int j=0;j<2;j++){
        float4 v = *(const float4*)(src + i0 + j*4);
        __half2 h0=__floats2half2_rn(v.x,v.y), h1=__floats2half2_rn(v.z,v.w);
        uint2 u; u.x=*(uint32_t*)&h0; u.y=*(uint32_t*)&h1;
        *(uint2*)(dst + i0 + j*4) = u;
    }
}

// =====================================================================
// K1: fused QKV. Block 128(t) x 192(n=3z x 64d), one head. 8 warps
// (2m x 4n) of 64x48. k-chunk 32, double-buffered cp.async.
// smem: A 2x[128][40]h (20KB) + B 2x 3x[32][72]h (27KB) = 47KB.
// =====================================================================
__global__ __launch_bounds__(256) void qkv_kernel()
{
    __shared__ __half As[2][128*40];
    __shared__ __half Bs[2][3*32*72];
    int tid=threadIdx.x, lane=tid&31, w=tid>>5;
    int g=lane>>2, tg=lane&3;
    int wm=w&1, wn=w>>1;
    int bh=blockIdx.y, b=bh>>4, h=bh&15;
    int m0=blockIdx.x*128;
    const __half* xb = g_xh + ((size_t)b*T_+m0)*C_;
    __half* outz[3] = { g_qh + ((size_t)bh*T_+m0)*D_,
                        g_kh + ((size_t)bh*T_+m0)*D_,
                        g_vh + ((size_t)bh*T_+m0)*D_ };

    uint32_t asb[2]={(uint32_t)__cvta_generic_to_shared(As[0]),
                     (uint32_t)__cvta_generic_to_shared(As[1])};
    uint32_t bsb[2]={(uint32_t)__cvta_generic_to_shared(Bs[0]),
                     (uint32_t)__cvta_generic_to_shared(Bs[1])};

    int zj[6], nlj[6];
    #pragma unroll
    for(int j=0;j<6;j++){ int n=wn*48+j*8; zj[j]=n>>6; nlj[j]=n&63; }

    float4 c[4][6];
    #pragma unroll
    for(int i=0;i<4;i++)
        #pragma unroll
        for(int j=0;j<6;j++) c[i][j]=make_float4(0.f,0.f,0.f,0.f);

    const int NC = C_/32;   // 32 chunks
    // prefetch chunk 0 -> buf0
    {
        #pragma unroll
        for(int i=0;i<2;i++){
            int u=tid+i*256, r=u>>2, un=u&3;
            cpa16(asb[0] + (r*40+un*8)*2, xb + (size_t)r*C_ + un*8);
        }
        #pragma unroll
        for(int i=0;i<3;i++){
            int u=tid+i*256, z=u>>8, rem=u&255, r=rem>>3, un=rem&7;
            cpa16(bsb[0] + z*4608 + (r*72+un*8)*2,
                  g_wh + (((size_t)z*H_+h)*C_ + r)*D_ + un*8);
        }
        CP_COMMIT();
    }

    for(int ch=0; ch<NC; ch++){
        int p=ch&1;
        __syncthreads();          // prev compute on buf p done everywhere
        if(ch+1<NC){
            int k1=(ch+1)*32;
            #pragma unroll
            for(int i=0;i<2;i++){
                int u=tid+i*256, r=u>>2, un=u&3;
                cpa16(asb[p^1] + (r*40+un*8)*2, xb + (size_t)r*C_ + k1 + un*8);
            }
            #pragma unroll
            for(int i=0;i<3;i++){
                int u=tid+i*256, z=u>>8, rem=u&255, r=rem>>3, un=rem&7;
                cpa16(bsb[p^1] + z*4608 + (r*72+un*8)*2,
                      g_wh + (((size_t)z*H_+h)*C_ + k1 + r)*D_ + un*8);
            }
            CP_COMMIT();
            CP_WAIT1();           // chunk ch landed
        } else {
            CP_WAIT0();
        }
        __syncthreads();

        uint32_t aoff = asb[p] + (ROWA(lane)*40 + KOFA(lane))*2;
        uint32_t btof = bsb[p] + (ROWT(lane)*72)*2;
        #pragma unroll
        for(int ks=0;ks<2;ks++){
            uint32_t a[4][4], bb[6][2];
            #pragma unroll
            for(int i=0;i<4;i++) ldmA(a[i], aoff + ((wm*4+i)*16*40 + ks*16)*2);
            #pragma unroll
            for(int j=0;j<6;j++) ldmBT(bb[j], btof + (zj[j]*2304 + ks*16*72 + nlj[j])*2);
            #pragma unroll
            for(int i=0;i<4;i++)
                #pragma unroll
                for(int j=0;j<6;j++) mma16(c[i][j], a[i], bb[j]);
        }
    }
    #pragma unroll
    for(int i=0;i<4;i++){
        int m=wm*64+i*16+g;
        #pragma unroll
        for(int j=0;j<6;j++){
            int d=nlj[j]+2*tg;
            __half* oz=outz[zj[j]];
            *(__half2*)(oz+(size_t)m*D_+d)     = __floats2half2_rn(c[i][j].x, c[i][j].y);
            *(__half2*)(oz+(size_t)(m+8)*D_+d) = __floats2half2_rn(c[i][j].z, c[i][j].w);
        }
    }
}

// =====================================================================
// K2: per-key Z via S^T = K.Q^T (R12-passing version, unchanged).
// =====================================================================
__global__ __launch_bounds__(256) void colsum_kernel()
{
    __shared__ __half Kf[128*72];
    __shared__ __half Qf[2][64*72];
    __shared__ float zsh[128];
    int tid=threadIdx.x, lane=tid&31, w=tid>>5;
    int g=lane>>2, tg=lane&3;
    int wm=w&3, wn=w>>2;
    int bh=blockIdx.y, s0=blockIdx.x*128;
    const __half* kb=g_kh+(size_t)bh*T_*D_;
    const __half* qb=g_qh+(size_t)bh*T_*D_;

    uint32_t ksb=(uint32_t)__cvta_generic_to_shared(Kf);
    uint32_t qsb[2]={(uint32_t)__cvta_generic_to_shared(Qf[0]),
                     (uint32_t)__cvta_generic_to_shared(Qf[1])};
    uint32_t aoff = ksb + (ROWA(lane)*72 + KOFA(lane))*2;

    if(tid<128) zsh[tid]=0.f;
    #pragma unroll
    for(int i=0;i<4;i++){
        int idx=tid+i*256, r=idx>>3, c8=(idx&7)*8;
        *(uint4*)&Kf[r*72+c8] = *(const uint4*)(kb+(size_t)(s0+r)*D_+c8);
    }
    #pragma unroll
    for(int i=0;i<2;i++){
        int idx=tid+i*256, rr=idx>>3, cc=(idx&7)*8;
        cpa16(qsb[0] + (rr*72+cc)*2, qb+(size_t)(s0+rr)*D_+cc);
    }
    CP_COMMIT();

    float zrow[2][2];
    zrow[0][0]=zrow[0][1]=zrow[1][0]=zrow[1][1]=0.f;

    for(int t0=s0; t0<T_; t0+=64){
        int p=((t0-s0)>>6)&1;
        CP_WAIT0();
        __syncthreads();
        if(t0+64<T_){
            #pragma unroll
            for(int i=0;i<2;i++){
                int idx=tid+i*256, rr=idx>>3, cc=(idx&7)*8;
                cpa16(qsb[p^1] + (rr*72+cc)*2, qb+(size_t)(t0+64+rr)*D_+cc);
            }
        }
        CP_COMMIT();
        uint32_t boff = qsb[p] + (ROWB(lane)*72 + KOFB(lane))*2;

        float4 c[2][4];
        #pragma unroll
        for(int i=0;i<2;i++)
            #pragma unroll
            for(int j=0;j<4;j++) c[i][j]=make_float4(0.f,0.f,0.f,0.f);
        #pragma unroll
        for(int ks=0;ks<4;ks++){
            uint32_t a[2][4], bb[4][2];
            #pragma unroll
            for(int i=0;i<2;i++) ldmA(a[i], aoff + ((wm*2+i)*16*72 + ks*16)*2);
            #pragma unroll
            for(int j=0;j<4;j++) ldmB(bb[j], boff + ((wn*4+j)*8*72 + ks*16)*2);
            #pragma unroll
            for(int i=0;i<2;i++)
                #pragma unroll
                for(int j=0;j<4;j++) mma16(c[i][j], a[i], bb[j]);
        }
        bool full = (t0 - s0) >= 128;
        #pragma unroll
        for(int i=0;i<2;i++){
            int sr0=s0+wm*32+i*16+g, sr1=sr0+8;
            #pragma unroll
            for(int j=0;j<4;j++){
                int tc0=t0+wn*32+j*8+2*tg, tc1=tc0+1;
                float4 S=c[i][j];
                zrow[i][0] += (full||tc0>=sr0)?__expf(S.x*0.125f):0.f;
                zrow[i][0] += (full||tc1>=sr0)?__expf(S.y*0.125f):0.f;
                zrow[i][1] += (full||tc0>=sr1)?__expf(S.z*0.125f):0.f;
                zrow[i][1] += (full||tc1>=sr1)?__expf(S.w*0.125f):0.f;
            }
        }
    }
    __syncthreads();
    #pragma unroll
    for(int i=0;i<2;i++)
        #pragma unroll
        for(int rr=0;rr<2;rr++){
            float v=zrow[i][rr];
            v += __shfl_xor_sync(0xffffffffu, v, 1);
            v += __shfl_xor_sync(0xffffffffu, v, 2);
            if(tg==0) atomicAdd(&zsh[wm*32+i*16+g+rr*8], v);
        }
    __syncthreads();
    if(tid<128) g_invZ[(size_t)bh*T_+s0+tid]=1.0f/zsh[tid];
}

// =====================================================================
// K3: attention (R12-passing version, unchanged).
// =====================================================================
__global__ __launch_bounds__(256) void attn_kernel()
{
    __shared__ __half Qf[128*72];
    __shared__ __half Kf[2][32*72];
    __shared__ __half Vf[2][32*72];
    __shared__ __half Pf[128*40];
    int tid=threadIdx.x, lane=tid&31, w=tid>>5;
    int g=lane>>2, tg=lane&3;
    int wq=w&3, wn=w>>2;
    int bh=blockIdx.y;
    int t0=((int)gridDim.x-1-(int)blockIdx.x)*128;
    const __half* qb=g_qh+(size_t)bh*T_*D_;
    const __half* kb=g_kh+(size_t)bh*T_*D_;
    const __half* vb=g_vh+(size_t)bh*T_*D_;
    const float* iz=g_invZ+(size_t)bh*T_;

    uint32_t qsb=(uint32_t)__cvta_generic_to_shared(Qf);
    uint32_t ksb[2]={(uint32_t)__cvta_generic_to_shared(Kf[0]),
                     (uint32_t)__cvta_generic_to_shared(Kf[1])};
    uint32_t vsb[2]={(uint32_t)__cvta_generic_to_shared(Vf[0]),
                     (uint32_t)__cvta_generic_to_shared(Vf[1])};
    uint32_t psb=(uint32_t)__cvta_generic_to_shared(Pf);
    uint32_t qAoff = qsb + (ROWA(lane)*72 + KOFA(lane))*2;
    uint32_t pAoff = psb + (ROWA(lane)*40 + KOFA(lane))*2;

    {
        int r=tid>>3, c8=(tid&7)*8;
        cpa16(ksb[0] + (r*72+c8)*2, kb+(size_t)r*D_+c8);
        cpa16(vsb[0] + (r*72+c8)*2, vb+(size_t)r*D_+c8);
    }
    CP_COMMIT();
    #pragma unroll
    for(int i=0;i<4;i++){
        int idx=tid+i*256, r=idx>>3, c8=(idx&7)*8;
        *(uint4*)&Qf[r*72+c8] = *(const uint4*)(qb+(size_t)(t0+r)*D_+c8);
    }

    float4 oacc[2][4];
    #pragma unroll
    for(int i=0;i<2;i++)
        #pragma unroll
        for(int j=0;j<4;j++) oacc[i][j]=make_float4(0.f,0.f,0.f,0.f);

    int send=t0+96;
    for(int s0=0; s0<=send; s0+=32){
        int p=(s0>>5)&1;
        CP_WAIT0();
        __syncthreads();
        if(s0+32<=send){
            int r=tid>>3, c8=(tid&7)*8;
            cpa16(ksb[p^1] + (r*72+c8)*2, kb+(size_t)(s0+32+r)*D_+c8);
            cpa16(vsb[p^1] + (r*72+c8)*2, vb+(size_t)(s0+32+r)*D_+c8);
        }
        CP_COMMIT();
        uint32_t kBoff = ksb[p] + (ROWB(lane)*72 + KOFB(lane))*2;
        uint32_t vToff = vsb[p] + (ROWT(lane)*72)*2;

        float4 s1[2][2];
        s1[0][0]=s1[0][1]=s1[1][0]=s1[1][1]=make_float4(0.f,0.f,0.f,0.f);
        #pragma unroll
        for(int ks=0;ks<4;ks++){
            uint32_t a[2][4], bb[2][2];
            #pragma unroll
            for(int i=0;i<2;i++) ldmA(a[i], qAoff + ((wq*2+i)*16*72 + ks*16)*2);
            #pragma unroll
            for(int j=0;j<2;j++) ldmB(bb[j], kBoff + ((wn*2+j)*8*72 + ks*16)*2);
            #pragma unroll
            for(int i=0;i<2;i++)
                #pragma unroll
                for(int j=0;j<2;j++) mma16(s1[i][j], a[i], bb[j]);
        }
        bool msk=(s0>=t0);
        #pragma unroll
        for(int i=0;i<2;i++){
            int ql0=wq*32+i*16+g;
            int qg0=t0+ql0, qg1=qg0+8;
            #pragma unroll
            for(int j=0;j<2;j++){
                int sl0=wn*16+j*8+2*tg, sl1=sl0+1;
                int sg0=s0+sl0, sg1=sg0+1;
                float iz0=__ldg(iz+sg0), iz1=__ldg(iz+sg1);
                float4 S=s1[i][j];
                float w00=(!msk||qg0>=sg0)?__expf(S.x*0.125f)*iz0:0.f;
                float w01=(!msk||qg0>=sg1)?__expf(S.y*0.125f)*iz1:0.f;
                float w10=(!msk||qg1>=sg0)?__expf(S.z*0.125f)*iz0:0.f;
                float w11=(!msk||qg1>=sg1)?__expf(S.w*0.125f)*iz1:0.f;
                *(__half2*)&Pf[ql0*40+sl0]     = __floats2half2_rn(w00, w01);
                *(__half2*)&Pf[(ql0+8)*40+sl0] = __floats2half2_rn(w10, w11);
            }
        }
        __syncthreads();

        #pragma unroll
        for(int ks=0;ks<2;ks++){
            uint32_t a[2][4], bb[4][2];
            #pragma unroll
            for(int i=0;i<2;i++) ldmA(a[i], pAoff + ((wq*2+i)*16*40 + ks*16)*2);
            #pragma unroll
            for(int j=0;j<4;j++) ldmBT(bb[j], vToff + (ks*16*72 + (wn*4+j)*8)*2);
            #pragma unroll
            for(int i=0;i<2;i++)
                #pragma unroll
                for(int j=0;j<4;j++) mma16(oacc[i][j], a[i], bb[j]);
        }
    }

    __half* ob=g_att+((size_t)bh*T_+t0)*D_;
    #pragma unroll
    for(int i=0;i<2;i++){
        int q=wq*32+i*16+g;
        #pragma unroll
        for(int j=0;j<4;j++){
            int d=wn*32+j*8+2*tg;
            *(__half2*)(ob+(size_t)q*D_+d)     = __floats2half2_rn(oacc[i][j].x, oacc[i][j].y);
            *(__half2*)(ob+(size_t)(q+8)*D_+d) = __floats2half2_rn(oacc[i][j].z, oacc[i][j].w);
        }
    }
}

// =====================================================================
// K4: output projection + bias. Block 128m x 128n, 8 warps (2m x 4n) of
// 64x32. k-chunk 32, double-buffered cp.async. smem 37KB.
// =====================================================================
__global__ __launch_bounds__(256) void oproj_kernel(
    const float* __restrict__ bo, float* __restrict__ out)
{
    __shared__ __half As[2][128*40];
    __shared__ __half Bs[2][32*136];
    int tid=threadIdx.x, lane=tid&31, w=tid>>5;
    int g=lane>>2, tg=lane&3;
    int wm=w&1, wn=w>>1;
    int m0=blockIdx.x*128, n0=blockIdx.y*128;

    uint32_t asb[2]={(uint32_t)__cvta_generic_to_shared(As[0]),
                     (uint32_t)__cvta_generic_to_shared(As[1])};
    uint32_t bsb[2]={(uint32_t)__cvta_generic_to_shared(Bs[0]),
                     (uint32_t)__cvta_generic_to_shared(Bs[1])};

    float4 c[4][4];
    #pragma unroll
    for(int i=0;i<4;i++)
        #pragma unroll
        for(int j=0;j<4;j++) c[i][j]=make_float4(0.f,0.f,0.f,0.f);

    const int NC = C_/32;
    // A fill helper indices: chunk k0 -> head hk=k0>>6, dk=k0&63
    auto prefetch = [&](int ch, int p){
        int k0=ch*32, hk=k0>>6, dk=k0&32 ? 32 : 0;
        #pragma unroll
        for(int i=0;i<2;i++){
            int u=tid+i*256, r=u>>2, un=u&3;
            int mg=m0+r, b=mg>>11, t=mg&2047;
            cpa16(asb[p] + (r*40+un*8)*2,
                  g_att + (((size_t)(b*H_+hk))*T_+t)*D_ + dk + un*8);
        }
        #pragma unroll
        for(int i=0;i<2;i++){
            int u=tid+i*256, r=u>>4, un=u&15;
            cpa16(bsb[p] + (r*136+un*8)*2,
                  g_woh + (size_t)(k0+r)*C_ + n0 + un*8);
        }
        CP_COMMIT();
    };

    prefetch(0, 0);
    for(int ch=0; ch<NC; ch++){
        int p=ch&1;
        __syncthreads();
        if(ch+1<NC){ prefetch(ch+1, p^1); CP_WAIT1(); }
        else       { CP_WAIT0(); }
        __syncthreads();

        uint32_t aoff = asb[p] + (ROWA(lane)*40 + KOFA(lane))*2;
        uint32_t btof = bsb[p] + (ROWT(lane)*136)*2;
        #pragma unroll
        for(int ks=0;ks<2;ks++){
            uint32_t a[4][4], bb[4][2];
            #pragma unroll
            for(int i=0;i<4;i++) ldmA(a[i], aoff + ((wm*4+i)*16*40 + ks*16)*2);
            #pragma unroll
            for(int j=0;j<4;j++) ldmBT(bb[j], btof + (ks*16*136 + (wn*4+j)*8)*2);
            #pragma unroll
            for(int i=0;i<4;i++)
                #pragma unroll
                for(int j=0;j<4;j++) mma16(c[i][j], a[i], bb[j]);
        }
    }
    #pragma unroll
    for(int i=0;i<4;i++){
        int m=m0+wm*64+i*16+g;
        #pragma unroll
        for(int j=0;j<4;j++){
            int n=n0+wn*32+j*8+2*tg;
            float b0v=bo[n], b1v=bo[n+1];
            *(float2*)(out+(size_t)m*C_+n)     = make_float2(c[i][j].x+b0v, c[i][j].y+b1v);
            *(float2*)(out+(size_t)(m+8)*C_+n) = make_float2(c[i][j].z+b0v, c[i][j].w+b1v);
        }
    }
}

// =====================================================================
extern "C" void kernel_launch(void* const* d_in, const int* in_sizes, int n_in,
                              void* d_out, int out_size)
{
    const float* x  = (const float*)d_in[0];
    const float* Wq = (const float*)d_in[1];
    const float* Wk = (const float*)d_in[2];
    const float* Wv = (const float*)d_in[3];
    const float* Wo = (const float*)d_in[4];
    const float* bo = (const float*)d_in[5];
    float* out = (float*)d_out;

    __half *xh, *wh, *woh;
    cudaGetSymbolAddress((void**)&xh,  g_xh);
    cudaGetSymbolAddress((void**)&wh,  g_wh);
    cudaGetSymbolAddress((void**)&woh, g_woh);

    cvt_kernel<<<B_*T_*C_/2048, 256>>>(x,  xh);
    cvt_kernel<<<H_*C_*D_/2048, 256>>>(Wq, wh);
    cvt_kernel<<<H_*C_*D_/2048, 256>>>(Wk, wh +   (size_t)H_*C_*D_);
    cvt_kernel<<<H_*C_*D_/2048, 256>>>(Wv, wh + 2*(size_t)H_*C_*D_);
    cvt_kernel<<<C_*C_/2048,    256>>>(Wo, woh);

    qkv_kernel   <<<dim3(T_/128, BH_), 256>>>();
    colsum_kernel<<<dim3(T_/128, BH_), 256>>>();
    attn_kernel  <<<dim3(T_/128, BH_), 256>>>();
    oproj_kernel <<<dim3((B_*T_)/128, C_/128), 256>>>(bo, out);
}

// round 15
// speedup vs baseline: 3.8322x; 1.0161x over previous
#include <cuda_runtime.h>
#include <cuda_fp16.h>
#include <cstdint>

#define B_   4
#define H_   16
#define T_   2048
#define C_   1024
#define D_   64
#define BH_  64

__device__ __half g_qh [BH_*T_*D_];
__device__ __half g_kh [BH_*T_*D_];
__device__ __half g_vh [BH_*T_*D_];
__device__ __half g_att[BH_*T_*D_];
__device__ float  g_invZ[BH_*T_];
__device__ __half g_xh [B_*T_*C_];       // x fp16
__device__ __half g_wh [3*H_*C_*D_];     // Wq/Wk/Wv fp16, layout [z][h][c][d]
__device__ __half g_woh[C_*C_];          // Wo fp16, layout [c][n]

// ================= helpers =================
__device__ __forceinline__ void mma16(float4 &c, const uint32_t* a, const uint32_t* b){
    asm volatile("mma.sync.aligned.m16n8k16.row.col.f32.f16.f16.f32 "
        "{%0,%1,%2,%3}, {%4,%5,%6,%7}, {%8,%9}, {%0,%1,%2,%3};"
        : "+f"(c.x), "+f"(c.y), "+f"(c.z), "+f"(c.w)
        : "r"(a[0]), "r"(a[1]), "r"(a[2]), "r"(a[3]), "r"(b[0]), "r"(b[1]));
}
__device__ __forceinline__ void ldmA(uint32_t* r, uint32_t addr){
    asm volatile("ldmatrix.sync.aligned.m8n8.x4.shared.b16 {%0,%1,%2,%3}, [%4];"
        : "=r"(r[0]), "=r"(r[1]), "=r"(r[2]), "=r"(r[3]) : "r"(addr));
}
__device__ __forceinline__ void ldmB(uint32_t* r, uint32_t addr){
    asm volatile("ldmatrix.sync.aligned.m8n8.x2.shared.b16 {%0,%1}, [%2];"
        : "=r"(r[0]), "=r"(r[1]) : "r"(addr));
}
__device__ __forceinline__ void ldmBT(uint32_t* r, uint32_t addr){
    asm volatile("ldmatrix.sync.aligned.m8n8.x2.trans.shared.b16 {%0,%1}, [%2];"
        : "=r"(r[0]), "=r"(r[1]) : "r"(addr));
}
__device__ __forceinline__ void cpa16(uint32_t dst, const void* src){
    asm volatile("cp.async.cg.shared.global [%0], [%1], 16;" :: "r"(dst), "l"(src));
}
#define CP_COMMIT() asm volatile("cp.async.commit_group;" ::: "memory")
#define CP_WAIT0()  asm volatile("cp.async.wait_group 0;"  ::: "memory")
#define CP_WAIT1()  asm volatile("cp.async.wait_group 1;"  ::: "memory")
__device__ __forceinline__ uint32_t h2u(float a, float b){
    __half2 h = __floats2half2_rn(a, b);
    return *(uint32_t*)&h;
}

// lane addressing (units: halves)
#define ROWA(l) (((l)&7) + (((l)>>3)&1)*8)
#define KOFA(l) (((l)>>4)*8)
#define ROWB(l) ((l)&7)
#define KOFB(l) ((((l)>>3)&1)*8)
#define ROWT(l) (((l)&7) + (((l)>>3)&1)*8)

// ================= prep: fp32 -> fp16 converts =================
__global__ __launch_bounds__(256) void cvt_kernel(const float* __restrict__ src, __half* __restrict__ dst){
    int i0 = (blockIdx.x*256 + threadIdx.x)*8;
    #pragma unroll
    for(int j=0;j<2;j++){
        float4 v = *(const float4*)(src + i0 + j*4);
        __half2 h0=__floats2half2_rn(v.x,v.y), h1=__floats2half2_rn(v.z,v.w);
        uint2 u; u.x=*(uint32_t*)&h0; u.y=*(uint32_t*)&h1;
        *(uint2*)(dst + i0 + j*4) = u;
    }
}

// =====================================================================
// K1: fused QKV (R14-passing). Block 128(t) x 192(n), 8 warps (2m x 4n).
// =====================================================================
__global__ __launch_bounds__(256) void qkv_kernel()
{
    __shared__ __half As[2][128*40];
    __shared__ __half Bs[2][3*32*72];
    int tid=threadIdx.x, lane=tid&31, w=tid>>5;
    int g=lane>>2, tg=lane&3;
    int wm=w&1, wn=w>>1;
    int bh=blockIdx.y, b=bh>>4, h=bh&15;
    int m0=blockIdx.x*128;
    const __half* xb = g_xh + ((size_t)b*T_+m0)*C_;
    __half* outz[3] = { g_qh + ((size_t)bh*T_+m0)*D_,
                        g_kh + ((size_t)bh*T_+m0)*D_,
                        g_vh + ((size_t)bh*T_+m0)*D_ };

    uint32_t asb[2]={(uint32_t)__cvta_generic_to_shared(As[0]),
                     (uint32_t)__cvta_generic_to_shared(As[1])};
    uint32_t bsb[2]={(uint32_t)__cvta_generic_to_shared(Bs[0]),
                     (uint32_t)__cvta_generic_to_shared(Bs[1])};

    int zj[6], nlj[6];
    #pragma unroll
    for(int j=0;j<6;j++){ int n=wn*48+j*8; zj[j]=n>>6; nlj[j]=n&63; }

    float4 c[4][6];
    #pragma unroll
    for(int i=0;i<4;i++)
        #pragma unroll
        for(int j=0;j<6;j++) c[i][j]=make_float4(0.f,0.f,0.f,0.f);

    const int NC = C_/32;
    {
        #pragma unroll
        for(int i=0;i<2;i++){
            int u=tid+i*256, r=u>>2, un=u&3;
            cpa16(asb[0] + (r*40+un*8)*2, xb + (size_t)r*C_ + un*8);
        }
        #pragma unroll
        for(int i=0;i<3;i++){
            int u=tid+i*256, z=u>>8, rem=u&255, r=rem>>3, un=rem&7;
            cpa16(bsb[0] + z*4608 + (r*72+un*8)*2,
                  g_wh + (((size_t)z*H_+h)*C_ + r)*D_ + un*8);
        }
        CP_COMMIT();
    }

    for(int ch=0; ch<NC; ch++){
        int p=ch&1;
        __syncthreads();
        if(ch+1<NC){
            int k1=(ch+1)*32;
            #pragma unroll
            for(int i=0;i<2;i++){
                int u=tid+i*256, r=u>>2, un=u&3;
                cpa16(asb[p^1] + (r*40+un*8)*2, xb + (size_t)r*C_ + k1 + un*8);
            }
            #pragma unroll
            for(int i=0;i<3;i++){
                int u=tid+i*256, z=u>>8, rem=u&255, r=rem>>3, un=rem&7;
                cpa16(bsb[p^1] + z*4608 + (r*72+un*8)*2,
                      g_wh + (((size_t)z*H_+h)*C_ + k1 + r)*D_ + un*8);
            }
            CP_COMMIT();
            CP_WAIT1();
        } else {
            CP_WAIT0();
        }
        __syncthreads();

        uint32_t aoff = asb[p] + (ROWA(lane)*40 + KOFA(lane))*2;
        uint32_t btof = bsb[p] + (ROWT(lane)*72)*2;
        #pragma unroll
        for(int ks=0;ks<2;ks++){
            uint32_t a[4][4], bb[6][2];
            #pragma unroll
            for(int i=0;i<4;i++) ldmA(a[i], aoff + ((wm*4+i)*16*40 + ks*16)*2);
            #pragma unroll
            for(int j=0;j<6;j++) ldmBT(bb[j], btof + (zj[j]*2304 + ks*16*72 + nlj[j])*2);
            #pragma unroll
            for(int i=0;i<4;i++)
                #pragma unroll
                for(int j=0;j<6;j++) mma16(c[i][j], a[i], bb[j]);
        }
    }
    #pragma unroll
    for(int i=0;i<4;i++){
        int m=wm*64+i*16+g;
        #pragma unroll
        for(int j=0;j<6;j++){
            int d=nlj[j]+2*tg;
            __half* oz=outz[zj[j]];
            *(__half2*)(oz+(size_t)m*D_+d)     = __floats2half2_rn(c[i][j].x, c[i][j].y);
            *(__half2*)(oz+(size_t)(m+8)*D_+d) = __floats2half2_rn(c[i][j].z, c[i][j].w);
        }
    }
}

// =====================================================================
// K2: per-key Z via S^T = K.Q^T (R12/R14-passing, unchanged).
// =====================================================================
__global__ __launch_bounds__(256) void colsum_kernel()
{
    __shared__ __half Kf[128*72];
    __shared__ __half Qf[2][64*72];
    __shared__ float zsh[128];
    int tid=threadIdx.x, lane=tid&31, w=tid>>5;
    int g=lane>>2, tg=lane&3;
    int wm=w&3, wn=w>>2;
    int bh=blockIdx.y, s0=blockIdx.x*128;
    const __half* kb=g_kh+(size_t)bh*T_*D_;
    const __half* qb=g_qh+(size_t)bh*T_*D_;

    uint32_t ksb=(uint32_t)__cvta_generic_to_shared(Kf);
    uint32_t qsb[2]={(uint32_t)__cvta_generic_to_shared(Qf[0]),
                     (uint32_t)__cvta_generic_to_shared(Qf[1])};
    uint32_t aoff = ksb + (ROWA(lane)*72 + KOFA(lane))*2;

    if(tid<128) zsh[tid]=0.f;
    #pragma unroll
    for(int i=0;i<4;i++){
        int idx=tid+i*256, r=idx>>3, c8=(idx&7)*8;
        *(uint4*)&Kf[r*72+c8] = *(const uint4*)(kb+(size_t)(s0+r)*D_+c8);
    }
    #pragma unroll
    for(int i=0;i<2;i++){
        int idx=tid+i*256, rr=idx>>3, cc=(idx&7)*8;
        cpa16(qsb[0] + (rr*72+cc)*2, qb+(size_t)(s0+rr)*D_+cc);
    }
    CP_COMMIT();

    float zrow[2][2];
    zrow[0][0]=zrow[0][1]=zrow[1][0]=zrow[1][1]=0.f;

    for(int t0=s0; t0<T_; t0+=64){
        int p=((t0-s0)>>6)&1;
        CP_WAIT0();
        __syncthreads();
        if(t0+64<T_){
            #pragma unroll
            for(int i=0;i<2;i++){
                int idx=tid+i*256, rr=idx>>3, cc=(idx&7)*8;
                cpa16(qsb[p^1] + (rr*72+cc)*2, qb+(size_t)(t0+64+rr)*D_+cc);
            }
        }
        CP_COMMIT();
        uint32_t boff = qsb[p] + (ROWB(lane)*72 + KOFB(lane))*2;

        float4 c[2][4];
        #pragma unroll
        for(int i=0;i<2;i++)
            #pragma unroll
            for(int j=0;j<4;j++) c[i][j]=make_float4(0.f,0.f,0.f,0.f);
        #pragma unroll
        for(int ks=0;ks<4;ks++){
            uint32_t a[2][4], bb[4][2];
            #pragma unroll
            for(int i=0;i<2;i++) ldmA(a[i], aoff + ((wm*2+i)*16*72 + ks*16)*2);
            #pragma unroll
            for(int j=0;j<4;j++) ldmB(bb[j], boff + ((wn*4+j)*8*72 + ks*16)*2);
            #pragma unroll
            for(int i=0;i<2;i++)
                #pragma unroll
                for(int j=0;j<4;j++) mma16(c[i][j], a[i], bb[j]);
        }
        bool full = (t0 - s0) >= 128;
        #pragma unroll
        for(int i=0;i<2;i++){
            int sr0=s0+wm*32+i*16+g, sr1=sr0+8;
            #pragma unroll
            for(int j=0;j<4;j++){
                int tc0=t0+wn*32+j*8+2*tg, tc1=tc0+1;
                float4 S=c[i][j];
                zrow[i][0] += (full||tc0>=sr0)?__expf(S.x*0.125f):0.f;
                zrow[i][0] += (full||tc1>=sr0)?__expf(S.y*0.125f):0.f;
                zrow[i][1] += (full||tc0>=sr1)?__expf(S.z*0.125f):0.f;
                zrow[i][1] += (full||tc1>=sr1)?__expf(S.w*0.125f):0.f;
            }
        }
    }
    __syncthreads();
    #pragma unroll
    for(int i=0;i<2;i++)
        #pragma unroll
        for(int rr=0;rr<2;rr++){
            float v=zrow[i][rr];
            v += __shfl_xor_sync(0xffffffffu, v, 1);
            v += __shfl_xor_sync(0xffffffffu, v, 2);
            if(tg==0) atomicAdd(&zsh[wm*32+i*16+g+rr*8], v);
        }
    __syncthreads();
    if(tid<128) g_invZ[(size_t)bh*T_+s0+tid]=1.0f/zsh[tid];
}

// =====================================================================
// K3: attention with register P forwarding (FA2-style). Block 128 q,
// 32-key tiles, 8 warps each owning 16 q x all 32 s. No Pf, 1 sync/tile.
// smem: Qf 18KB + K 2x4.5KB + V 2x4.5KB = 36.9KB.
// =====================================================================
__global__ __launch_bounds__(256) void attn_kernel()
{
    __shared__ __half Qf[128*72];
    __shared__ __half Kf[2][32*72];
    __shared__ __half Vf[2][32*72];
    int tid=threadIdx.x, lane=tid&31, w=tid>>5;
    int g=lane>>2, tg=lane&3;
    int bh=blockIdx.y;
    int t0=((int)gridDim.x-1-(int)blockIdx.x)*128;   // big tiles first
    const __half* qb=g_qh+(size_t)bh*T_*D_;
    const __half* kb=g_kh+(size_t)bh*T_*D_;
    const __half* vb=g_vh+(size_t)bh*T_*D_;
    const float* iz=g_invZ+(size_t)bh*T_;

    uint32_t qsb=(uint32_t)__cvta_generic_to_shared(Qf);
    uint32_t ksb[2]={(uint32_t)__cvta_generic_to_shared(Kf[0]),
                     (uint32_t)__cvta_generic_to_shared(Kf[1])};
    uint32_t vsb[2]={(uint32_t)__cvta_generic_to_shared(Vf[0]),
                     (uint32_t)__cvta_generic_to_shared(Vf[1])};
    // warp's Q A-frag base: rows w*16 + ROWA
    uint32_t qAoff = qsb + ((w*16+ROWA(lane))*72 + KOFA(lane))*2;

    // preload first K/V tile
    {
        int r=tid>>3, c8=(tid&7)*8;
        cpa16(ksb[0] + (r*72+c8)*2, kb+(size_t)r*D_+c8);
        cpa16(vsb[0] + (r*72+c8)*2, vb+(size_t)r*D_+c8);
    }
    CP_COMMIT();
    #pragma unroll
    for(int i=0;i<4;i++){
        int idx=tid+i*256, r=idx>>3, c8=(idx&7)*8;
        *(uint4*)&Qf[r*72+c8] = *(const uint4*)(qb+(size_t)(t0+r)*D_+c8);
    }

    float4 oacc[8];
    #pragma unroll
    for(int j=0;j<8;j++) oacc[j]=make_float4(0.f,0.f,0.f,0.f);

    int qg0 = t0 + w*16 + g, qg1 = qg0 + 8;
    int send = t0 + 96;
    for(int s0=0; s0<=send; s0+=32){
        int p=(s0>>5)&1;
        CP_WAIT0();
        __syncthreads();   // K/V[p] visible to all; prev-iter reads of p^1 done
        if(s0+32<=send){
            int r=tid>>3, c8=(tid&7)*8;
            cpa16(ksb[p^1] + (r*72+c8)*2, kb+(size_t)(s0+32+r)*D_+c8);
            cpa16(vsb[p^1] + (r*72+c8)*2, vb+(size_t)(s0+32+r)*D_+c8);
        }
        CP_COMMIT();
        uint32_t kBoff = ksb[p] + (ROWB(lane)*72 + KOFB(lane))*2;
        uint32_t vToff = vsb[p] + (ROWT(lane)*72)*2;

        // stage1: S[16q x 32s] per warp (4 n8-tiles), K=64 (4 ks)
        float4 s1[4];
        #pragma unroll
        for(int j=0;j<4;j++) s1[j]=make_float4(0.f,0.f,0.f,0.f);
        #pragma unroll
        for(int ks=0;ks<4;ks++){
            uint32_t a[4], bb[4][2];
            ldmA(a, qAoff + (ks*16)*2);
            #pragma unroll
            for(int j=0;j<4;j++) ldmB(bb[j], kBoff + (j*8*72 + ks*16)*2);
            #pragma unroll
            for(int j=0;j<4;j++) mma16(s1[j], a, bb[j]);
        }

        // exp * invZ in registers, masked
        bool msk=(s0>=t0);
        float4 e[4];
        #pragma unroll
        for(int j=0;j<4;j++){
            int sg0=s0+j*8+2*tg, sg1=sg0+1;
            float iz0=__ldg(iz+sg0), iz1=__ldg(iz+sg1);
            float4 S=s1[j];
            e[j].x=(!msk||qg0>=sg0)?__expf(S.x*0.125f)*iz0:0.f;
            e[j].y=(!msk||qg0>=sg1)?__expf(S.y*0.125f)*iz1:0.f;
            e[j].z=(!msk||qg1>=sg0)?__expf(S.z*0.125f)*iz0:0.f;
            e[j].w=(!msk||qg1>=sg1)?__expf(S.w*0.125f)*iz1:0.f;
        }
        // pack C-frags -> A-frags: ks2=0 from tiles 0,1; ks2=1 from tiles 2,3
        uint32_t aP[2][4];
        #pragma unroll
        for(int k2=0;k2<2;k2++){
            aP[k2][0]=h2u(e[2*k2].x,   e[2*k2].y);
            aP[k2][1]=h2u(e[2*k2].z,   e[2*k2].w);
            aP[k2][2]=h2u(e[2*k2+1].x, e[2*k2+1].y);
            aP[k2][3]=h2u(e[2*k2+1].z, e[2*k2+1].w);
        }

        // stage2: O[16q x 64d] += P(16x32).V(32x64), 2 ks x 8 n8-tiles
        #pragma unroll
        for(int k2=0;k2<2;k2++){
            uint32_t bb[8][2];
            #pragma unroll
            for(int nt=0;nt<8;nt++) ldmBT(bb[nt], vToff + (k2*16*72 + nt*8)*2);
            #pragma unroll
            for(int nt=0;nt<8;nt++) mma16(oacc[nt], aP[k2], bb[nt]);
        }
    }

    __half* ob=g_att+((size_t)bh*T_+t0)*D_;
    int q0=w*16+g;
    #pragma unroll
    for(int nt=0;nt<8;nt++){
        int d=nt*8+2*tg;
        *(__half2*)(ob+(size_t)q0*D_+d)     = __floats2half2_rn(oacc[nt].x, oacc[nt].y);
        *(__half2*)(ob+(size_t)(q0+8)*D_+d) = __floats2half2_rn(oacc[nt].z, oacc[nt].w);
    }
}

// =====================================================================
// K4: output projection + bias (R14-passing, unchanged).
// =====================================================================
__global__ __launch_bounds__(256) void oproj_kernel(
    const float* __restrict__ bo, float* __restrict__ out)
{
    __shared__ __half As[2][128*40];
    __shared__ __half Bs[2][32*136];
    int tid=threadIdx.x, lane=tid&31, w=tid>>5;
    int g=lane>>2, tg=lane&3;
    int wm=w&1, wn=w>>1;
    int m0=blockIdx.x*128, n0=blockIdx.y*128;

    uint32_t asb[2]={(uint32_t)__cvta_generic_to_shared(As[0]),
                     (uint32_t)__cvta_generic_to_shared(As[1])};
    uint32_t bsb[2]={(uint32_t)__cvta_generic_to_shared(Bs[0]),
                     (uint32_t)__cvta_generic_to_shared(Bs[1])};

    float4 c[4][4];
    #pragma unroll
    for(int i=0;i<4;i++)
        #pragma unroll
        for(int j=0;j<4;j++) c[i][j]=make_float4(0.f,0.f,0.f,0.f);

    const int NC = C_/32;
    auto prefetch = [&](int ch, int p){
        int k0=ch*32, hk=k0>>6, dk=k0&32 ? 32 : 0;
        #pragma unroll
        for(int i=0;i<2;i++){
            int u=tid+i*256, r=u>>2, un=u&3;
            int mg=m0+r, b=mg>>11, t=mg&2047;
            cpa16(asb[p] + (r*40+un*8)*2,
                  g_att + (((size_t)(b*H_+hk))*T_+t)*D_ + dk + un*8);
        }
        #pragma unroll
        for(int i=0;i<2;i++){
            int u=tid+i*256, r=u>>4, un=u&15;
            cpa16(bsb[p] + (r*136+un*8)*2,
                  g_woh + (size_t)(k0+r)*C_ + n0 + un*8);
        }
        CP_COMMIT();
    };

    prefetch(0, 0);
    for(int ch=0; ch<NC; ch++){
        int p=ch&1;
        __syncthreads();
        if(ch+1<NC){ prefetch(ch+1, p^1); CP_WAIT1(); }
        else       { CP_WAIT0(); }
        __syncthreads();

        uint32_t aoff = asb[p] + (ROWA(lane)*40 + KOFA(lane))*2;
        uint32_t btof = bsb[p] + (ROWT(lane)*136)*2;
        #pragma unroll
        for(int ks=0;ks<2;ks++){
            uint32_t a[4][4], bb[4][2];
            #pragma unroll
            for(int i=0;i<4;i++) ldmA(a[i], aoff + ((wm*4+i)*16*40 + ks*16)*2);
            #pragma unroll
            for(int j=0;j<4;j++) ldmBT(bb[j], btof + (ks*16*136 + (wn*4+j)*8)*2);
            #pragma unroll
            for(int i=0;i<4;i++)
                #pragma unroll
                for(int j=0;j<4;j++) mma16(c[i][j], a[i], bb[j]);
        }
    }
    #pragma unroll
    for(int i=0;i<4;i++){
        int m=m0+wm*64+i*16+g;
        #pragma unroll
        for(int j=0;j<4;j++){
            int n=n0+wn*32+j*8+2*tg;
            float b0v=bo[n], b1v=bo[n+1];
            *(float2*)(out+(size_t)m*C_+n)     = make_float2(c[i][j].x+b0v, c[i][j].y+b1v);
            *(float2*)(out+(size_t)(m+8)*C_+n) = make_float2(c[i][j].z+b0v, c[i][j].w+b1v);
        }
    }
}

// =====================================================================
extern "C" void kernel_launch(void* const* d_in, const int* in_sizes, int n_in,
                              void* d_out, int out_size)
{
    const float* x  = (const float*)d_in[0];
    const float* Wq = (const float*)d_in[1];
    const float* Wk = (const float*)d_in[2];
    const float* Wv = (const float*)d_in[3];
    const float* Wo = (const float*)d_in[4];
    const float* bo = (const float*)d_in[5];
    float* out = (float*)d_out;

    __half *xh, *wh, *woh;
    cudaGetSymbolAddress((void**)&xh,  g_xh);
    cudaGetSymbolAddress((void**)&wh,  g_wh);
    cudaGetSymbolAddress((void**)&woh, g_woh);

    cvt_kernel<<<B_*T_*C_/2048, 256>>>(x,  xh);
    cvt_kernel<<<H_*C_*D_/2048, 256>>>(Wq, wh);
    cvt_kernel<<<H_*C_*D_/2048, 256>>>(Wk, wh +   (size_t)H_*C_*D_);
    cvt_kernel<<<H_*C_*D_/2048, 256>>>(Wv, wh + 2*(size_t)H_*C_*D_);
    cvt_kernel<<<C_*C_/2048,    256>>>(Wo, woh);

    qkv_kernel   <<<dim3(T_/128, BH_), 256>>>();
    colsum_kernel<<<dim3(T_/128, BH_), 256>>>();
    attn_kernel  <<<dim3(T_/128, BH_), 256>>>();
    oproj_kernel <<<dim3((B_*T_)/128, C_/128), 256>>>(bo, out);
}